// round 9
// baseline (speedup 1.0000x reference)
#include <cuda_runtime.h>
#include <cstdint>
#include <cfloat>

#define NMAX 100000
#define BMAX 64
#define DD   256
#define TT   4
#define HH   32
#define K2CH 512

// ---------------- scratch (static __device__, no allocation) ----------------
__device__ float         g_targets[BMAX * DD];
__device__ unsigned      g_tbits[BMAX * 4];
__device__ unsigned      g_abits[NMAX * 4];
__device__ unsigned char g_dist_t[(size_t)NMAX * BMAX];   // [n][b]
__device__ unsigned      g_hist[BMAX * 129];
__device__ int           g_dstar[BMAX];
__device__ int           g_r[BMAX];
__device__ int           g_istar[BMAX];
__device__ unsigned      g_cnt[200 * BMAX];               // [chunk][b]
__device__ float         g_scores[(size_t)BMAX * NMAX];   // [b][n]
__device__ float         g_pv[BMAX * 16 * 10];
__device__ int           g_pi[BMAX * 16 * 10];

__device__ __forceinline__ unsigned smem_u32(const void* p) {
    unsigned a;
    asm("{ .reg .u64 t; cvta.to.shared.u64 t, %1; cvt.u32.u64 %0, t; }"
        : "=r"(a) : "l"(p));
    return a;
}
#define FFMA2(acc, a, b) \
    asm("fma.rn.f32x2 %0, %1, %2, %0;" : "+l"(acc) : "l"(a), "l"(b))

// ---------------- K0c: zero histograms (launch idx 0) -----------------------
__global__ void k0c_zero()
{
    int i = blockIdx.x * blockDim.x + threadIdx.x;
    if (i < BMAX * 129) g_hist[i] = 0u;
}

// ---------------- K0a: target embeddings (launch idx 1) ---------------------
__global__ void k0a_targets(const int* __restrict__ head,
                            const int* __restrict__ rel,
                            const float* __restrict__ eemb,
                            const float* __restrict__ remb)
{
    int b = blockIdx.x, tid = threadIdx.x;
    int hh = head[b], rr = rel[b];
    for (int d = tid; d < DD; d += blockDim.x)
        g_targets[b * DD + d] = eemb[(size_t)hh * DD + d] * remb[(size_t)rr * DD + d];
}

// ---------------- K0b: target hash bits (launch idx 2) ----------------------
__global__ void k0b_tbits(const float* __restrict__ proj)
{
    __shared__ float tgt[DD];
    int b = blockIdx.x, tid = threadIdx.x;
    for (int d = tid; d < DD; d += blockDim.x) tgt[d] = g_targets[b * DD + d];
    __syncthreads();
    int t = tid >> 5, lane = tid & 31;
    const float* pp = proj + (size_t)t * DD * HH + lane;
    float acc = 0.f;
#pragma unroll 8
    for (int d = 0; d < DD; d++) acc += tgt[d] * pp[d * HH];
    unsigned w = __ballot_sync(0xffffffffu, acc > 0.f);
    if (lane == 0) g_tbits[b * 4 + t] = w;
}

// ---------------- K1: entity hash bits v2 — FMA-pipe-bound ------------------
// Thread = 2 ents x 16 cols (4 interleaved quads). 64-ent tiles.
// projs[d*128 + c]: thread reads [d*512 + v*128 + cg*16] -> contiguous 128B/warp.
// ebuf[d*65 + e]: 65-float rows -> 4-way staging conflicts only.
__global__ __launch_bounds__(256, 1)
void k1_entity_bits(const float* __restrict__ eemb,
                    const float* __restrict__ proj, int N)
{
    extern __shared__ float sm[];
    float* projs = sm;               // 32768 floats (128KB)
    float* ebuf  = sm + 32768;       // 256*65 = 16640 floats (65KB)

    int tid  = threadIdx.x;
    int w    = tid >> 5, lane = tid & 31;
    int cg   = lane >> 2;            // 0..7 column quad
    int es   = lane & 3;             // 0..3 entity pair slot
    int e0i  = 8 * w + 2 * es;       // thread's entities within tile
    int e1i  = e0i + 1;

    unsigned pb0 = smem_u32(projs) + (unsigned)(cg * 16);
    unsigned eb0 = smem_u32(ebuf) + (unsigned)(e0i * 4);

    // stage projection: proj[t][d][h] -> projs[d*128 + t*32 + h]
    for (int i = tid; i < TT * DD * HH; i += 256) {
        int tt = i >> 13, d = (i >> 5) & 255, h = i & 31;
        projs[d * 128 + tt * 32 + h] = proj[i];
    }

    int tiles = (N + 63) >> 6;
    int per = (tiles + gridDim.x - 1) / gridDim.x;
    int t0 = blockIdx.x * per, t1 = min(tiles, t0 + per);
    if (t0 >= t1) return;            // whole block exits

    float4 pf[16];
    {
        int base = t0 * 64;
        const float4* src = (const float4*)(eemb + (size_t)base * DD);
        int limit = min(64, N - base) * 64;
#pragma unroll
        for (int k = 0; k < 16; k++) {
            int idx = tid + k * 256;
            pf[k] = (idx < limit) ? src[idx] : make_float4(0.f, 0.f, 0.f, 0.f);
        }
    }
    __syncthreads();                 // projs ready

    for (int tile = t0; tile < t1; tile++) {
        // store prefetched 64-ent tile: ebuf[(4*d4+i)*65 + e]
#pragma unroll
        for (int k = 0; k < 16; k++) {
            int idx = tid + k * 256;
            int e = idx >> 6, d4 = idx & 63;
            float* dst = ebuf + d4 * 260 + e;
            dst[0]   = pf[k].x;
            dst[65]  = pf[k].y;
            dst[130] = pf[k].z;
            dst[195] = pf[k].w;
        }
        __syncthreads();

        if (tile + 1 < t1) {         // next-tile LDGs fly over compute
            int base = (tile + 1) * 64;
            const float4* src = (const float4*)(eemb + (size_t)base * DD);
            int limit = min(64, N - base) * 64;
#pragma unroll
            for (int k = 0; k < 16; k++) {
                int idx = tid + k * 256;
                pf[k] = (idx < limit) ? src[idx] : make_float4(0.f, 0.f, 0.f, 0.f);
            }
        }

        unsigned long long acc[16];
#pragma unroll
        for (int i = 0; i < 16; i++) acc[i] = 0ull;

        unsigned pb = pb0, eb = eb0;
        for (int d4 = 0; d4 < 64; d4++) {
#pragma unroll
            for (int i = 0; i < 4; i++) {
                float e0v, e1v;
                asm("ld.shared.f32 %0, [%1];" : "=f"(e0v) : "r"(eb + (unsigned)(i * 260)));
                asm("ld.shared.f32 %0, [%1];" : "=f"(e1v) : "r"(eb + (unsigned)(i * 260 + 4)));
                unsigned long long pe0, pe1;
                asm("mov.b64 %0, {%1,%1};" : "=l"(pe0) : "f"(e0v));
                asm("mov.b64 %0, {%1,%1};" : "=l"(pe1) : "f"(e1v));
#pragma unroll
                for (int v = 0; v < 4; v++) {
                    unsigned long long pa, pc;
                    asm("ld.shared.v2.b64 {%0,%1}, [%2];" : "=l"(pa), "=l"(pc)
                        : "r"(pb + (unsigned)(i * 512 + v * 128)));
                    FFMA2(acc[v * 4 + 0], pa, pe0);
                    FFMA2(acc[v * 4 + 1], pc, pe0);
                    FFMA2(acc[v * 4 + 2], pa, pe1);
                    FFMA2(acc[v * 4 + 3], pc, pe1);
                }
            }
            pb += 2048;              // 4 d-rows of 512B
            eb += 1040;              // 4 d-rows of 260B
        }

        // sign words: word v covers cols 32v..32v+31; thread's nibble at 4*cg
        int base = tile * 64;
#pragma unroll
        for (int v = 0; v < 4; v++) {
            unsigned nib0 = 0, nib1 = 0;
#pragma unroll
            for (int h = 0; h < 2; h++) {
                float lo, hi;
                asm("mov.b64 {%0,%1}, %2;" : "=f"(lo), "=f"(hi) : "l"(acc[v * 4 + h]));
                nib0 |= (lo > 0.f ? 1u : 0u) << (2 * h);
                nib0 |= (hi > 0.f ? 1u : 0u) << (2 * h + 1);
                asm("mov.b64 {%0,%1}, %2;" : "=f"(lo), "=f"(hi) : "l"(acc[v * 4 + 2 + h]));
                nib1 |= (lo > 0.f ? 1u : 0u) << (2 * h);
                nib1 |= (hi > 0.f ? 1u : 0u) << (2 * h + 1);
            }
            unsigned w0 = nib0 << (4 * cg), w1 = nib1 << (4 * cg);
#pragma unroll
            for (int m = 4; m <= 16; m <<= 1) {
                w0 |= __shfl_xor_sync(0xffffffffu, w0, m);
                w1 |= __shfl_xor_sync(0xffffffffu, w1, m);
            }
            if (cg == v) {
                if (base + e0i < N) g_abits[(size_t)(base + e0i) * 4 + v] = w0;
                if (base + e1i < N) g_abits[(size_t)(base + e1i) * 4 + v] = w1;
            }
        }
        __syncthreads();             // ebuf reuse
    }
}

// ---------------- K2: hamming + histograms (warp-owns-query, no atomics) ----
__global__ __launch_bounds__(256)
void k2_hamming(int N)
{
    extern __shared__ unsigned char smraw[];
    uint4*         sab   = (uint4*)smraw;                  // 8192
    unsigned*      shist = (unsigned*)(smraw + 8192);      // 33792
    unsigned char* sdist = smraw + 8192 + 33792;           // [512][68]

    int tid = threadIdx.x, w = tid >> 5, lane = tid & 31;
    int base = blockIdx.x * K2CH;
    int cnt  = min(K2CH, N - base);

    for (int i = tid; i < BMAX * 132; i += 256) shist[i] = 0u;
    for (int i = tid; i < cnt * 4; i += 256)
        ((unsigned*)sab)[i] = g_abits[(size_t)base * 4 + i];
    __syncthreads();

    for (int q = w; q < BMAX; q += 8) {
        unsigned t0 = g_tbits[q * 4 + 0], t1 = g_tbits[q * 4 + 1];
        unsigned t2 = g_tbits[q * 4 + 2], t3 = g_tbits[q * 4 + 3];
        unsigned* hrow = shist + q * 132;
        for (int it = 0; it < 16; it++) {
            int i = it * 32 + lane;
            uint4 a = sab[i];
            unsigned d = __popc(a.x ^ t0) + __popc(a.y ^ t1)
                       + __popc(a.z ^ t2) + __popc(a.w ^ t3);
            unsigned d2 = (i < cnt) ? d : 0xffffffffu;
            if (i < cnt) sdist[i * 68 + q] = (unsigned char)d;
            unsigned mask = __match_any_sync(0xffffffffu, d2);
            if ((int)lane == __ffs(mask) - 1 && d2 != 0xffffffffu)
                hrow[d2] = hrow[d2] + __popc(mask);
        }
    }
    __syncthreads();

    for (int idx = tid; idx < K2CH * 16; idx += 256) {
        int i = idx >> 4, c = idx & 15;
        if (i < cnt)
            ((unsigned*)g_dist_t)[((size_t)(base + i)) * 16 + c] =
                *(const unsigned*)(sdist + i * 68 + c * 4);
    }
    for (int i = tid; i < BMAX * 129; i += 256) {
        int q = i / 129, d = i - q * 129;
        unsigned v = shist[q * 132 + d];
        if (v) atomicAdd(&g_hist[i], v);
    }
}

// ---------------- K3a: d*, r via parallel prefix scan -----------------------
__global__ void k3a(int CAND)
{
    __shared__ unsigned s[160];
    int q = blockIdx.x, tid = threadIdx.x;
    unsigned h = (tid < 129) ? g_hist[q * 129 + tid] : 0u;
    s[tid] = h;
    __syncthreads();
#pragma unroll
    for (int off = 1; off < 160; off <<= 1) {
        unsigned v = (tid >= off) ? s[tid - off] : 0u;
        __syncthreads();
        s[tid] += v;
        __syncthreads();
    }
    unsigned cum = s[tid];
    if (tid < 129 && cum >= (unsigned)CAND && cum - h < (unsigned)CAND) {
        g_dstar[q] = tid;
        g_r[q] = CAND - (int)(cum - h);
    }
}

// ---------------- K3b: per-chunk count of dist == d* ------------------------
__global__ __launch_bounds__(256) void k3b(int N)
{
    __shared__ unsigned char sd[K2CH * 68];
    __shared__ int sds[BMAX];
    int tid = threadIdx.x, w = tid >> 5, lane = tid & 31;
    int base = blockIdx.x * K2CH, cnt = min(K2CH, N - base);
    if (tid < BMAX) sds[tid] = g_dstar[tid];
    for (int idx = tid; idx < cnt * 16; idx += 256) {
        int i = idx >> 4, c = idx & 15;
        *(unsigned*)(sd + i * 68 + c * 4) =
            ((const unsigned*)g_dist_t)[((size_t)(base + i)) * 16 + c];
    }
    __syncthreads();
    for (int q = w; q < BMAX; q += 8) {
        int ds = sds[q]; unsigned c = 0;
        for (int it = 0; it < 16; it++) {
            int i = it * 32 + lane;
            int f = (i < cnt) && (sd[i * 68 + q] == ds);
            c += __popc(__ballot_sync(0xffffffffu, f));
        }
        if (lane == 0) g_cnt[blockIdx.x * BMAX + q] = c;
    }
}

// ---------------- K3c: index cutoff I* --------------------------------------
__global__ void k3c(int N, int nch)
{
    __shared__ unsigned scnt[256];
    __shared__ int s_c, s_rem;
    __shared__ unsigned char fl[K2CH];
    int q = blockIdx.x, tid = threadIdx.x;
    scnt[tid] = (tid < nch) ? g_cnt[tid * BMAX + q] : 0u;
    __syncthreads();
    if (tid == 0) {
        int r = g_r[q]; unsigned cum = 0; int c = 0;
        for (;; c++) {
            unsigned h = scnt[c];
            if (cum + h >= (unsigned)r) { s_c = c; s_rem = r - (int)cum; break; }
            cum += h;
        }
    }
    __syncthreads();
    int base = s_c * K2CH, ds = g_dstar[q];
    for (int i = tid; i < K2CH; i += blockDim.x) {
        int n = base + i;
        fl[i] = (n < N && g_dist_t[(size_t)n * BMAX + q] == (unsigned char)ds) ? 1 : 0;
    }
    __syncthreads();
    if (tid == 0) {
        int need = s_rem, c2 = 0, i = 0;
        for (;; i++) { c2 += fl[i]; if (c2 == need) break; }
        g_istar[q] = base + i;
    }
}

// ---------------- K4: candidate scores (gather; dense [B][N] fill) ----------
__global__ __launch_bounds__(256)
void k4_scores(const float* __restrict__ eemb, int N)
{
    extern __shared__ float sm4[];
    float* st   = sm4;                       // targets 64*256
    float* tile = sm4 + BMAX * DD;           // [64][32]
    int*   ds   = (int*)(tile + BMAX * 32);
    int*   is_  = ds + BMAX;

    int tid = threadIdx.x;
    for (int i = tid; i < BMAX * DD; i += blockDim.x) st[i] = g_targets[i];
    if (tid < BMAX) { ds[tid] = g_dstar[tid]; is_[tid] = g_istar[tid]; }
    for (int i = tid; i < BMAX * 32; i += blockDim.x) tile[i] = -FLT_MAX;
    __syncthreads();

    int base = blockIdx.x * 32;
    int w = tid >> 5, lane = tid & 31;

    for (int e = 0; e < 4; e++) {
        int i = w * 4 + e;
        int n = base + i;
        if (n >= N) continue;  // uniform per warp
        float4 r0 = *(const float4*)(eemb + (size_t)n * DD + lane * 8);
        float4 r1 = *(const float4*)(eemb + (size_t)n * DD + lane * 8 + 4);
        unsigned char d0 = g_dist_t[(size_t)n * BMAX + lane];
        unsigned char d1 = g_dist_t[(size_t)n * BMAX + 32 + lane];
        int b0 = lane, b1 = lane + 32;
        bool f0 = (d0 < ds[b0]) || (d0 == ds[b0] && n <= is_[b0]);
        bool f1 = (d1 < ds[b1]) || (d1 == ds[b1] && n <= is_[b1]);
        unsigned m0 = __ballot_sync(0xffffffffu, f0);
        unsigned m1 = __ballot_sync(0xffffffffu, f1);

        while (m0) {
            int b = __ffs(m0) - 1; m0 &= m0 - 1;
            const float4* tp = (const float4*)(st + b * DD + lane * 8);
            float4 t0 = tp[0], t1 = tp[1];
            float s = r0.x * t0.x + r0.y * t0.y + r0.z * t0.z + r0.w * t0.w
                    + r1.x * t1.x + r1.y * t1.y + r1.z * t1.z + r1.w * t1.w;
#pragma unroll
            for (int off = 16; off; off >>= 1) s += __shfl_xor_sync(0xffffffffu, s, off);
            if (lane == 0) tile[b * 32 + i] = s;
        }
        while (m1) {
            int b = 32 + __ffs(m1) - 1; m1 &= m1 - 1;
            const float4* tp = (const float4*)(st + b * DD + lane * 8);
            float4 t0 = tp[0], t1 = tp[1];
            float s = r0.x * t0.x + r0.y * t0.y + r0.z * t0.z + r0.w * t0.w
                    + r1.x * t1.x + r1.y * t1.y + r1.z * t1.z + r1.w * t1.w;
#pragma unroll
            for (int off = 16; off; off >>= 1) s += __shfl_xor_sync(0xffffffffu, s, off);
            if (lane == 0) tile[b * 32 + i] = s;
        }
    }
    __syncthreads();
    for (int idx = tid; idx < BMAX * 32; idx += blockDim.x) {
        int bb = idx >> 5, i = idx & 31;
        int n = base + i;
        if (n < N) g_scores[(size_t)bb * N + n] = tile[idx];
    }
}

// ---------------- K5a: per-segment top-10 in smem ---------------------------
#define SEG 6250
__global__ __launch_bounds__(256) void k5a(int N)
{
    extern __shared__ float sv[];            // SEG floats
    __shared__ float wv[8]; __shared__ int wi[8];
    int b = blockIdx.x >> 4, s = blockIdx.x & 15;
    int tid = threadIdx.x, w = tid >> 5, lane = tid & 31;
    int base = s * SEG;
    const float* src = g_scores + (size_t)b * N;
    for (int i = tid; i < SEG; i += 256)
        sv[i] = (base + i < N) ? src[base + i] : -FLT_MAX;
    __syncthreads();

    for (int p = 0; p < 10; p++) {
        float bv = -FLT_MAX; int bi = 1 << 30;
        for (int i = tid; i < SEG; i += 256) {
            float v = sv[i];
            if (v > bv) { bv = v; bi = i; }
        }
#pragma unroll
        for (int off = 16; off; off >>= 1) {
            float ov = __shfl_down_sync(0xffffffffu, bv, off);
            int   oi = __shfl_down_sync(0xffffffffu, bi, off);
            if (ov > bv || (ov == bv && oi < bi)) { bv = ov; bi = oi; }
        }
        if (lane == 0) { wv[w] = bv; wi[w] = bi; }
        __syncthreads();
        if (tid == 0) {
            float fv = wv[0]; int fi = wi[0];
            for (int x = 1; x < 8; x++)
                if (wv[x] > fv || (wv[x] == fv && wi[x] < fi)) { fv = wv[x]; fi = wi[x]; }
            g_pv[blockIdx.x * 10 + p] = fv;
            g_pi[blockIdx.x * 10 + p] = base + ((fi < SEG) ? fi : 0);
            if (fi < SEG) sv[fi] = -FLT_MAX;
        }
        __syncthreads();
    }
}

// ---------------- K5b: merge 16x10 -> top-k (one warp per query) ------------
__global__ void k5b(const int* __restrict__ kptr, float* __restrict__ out, int half)
{
    __shared__ float sv[160]; __shared__ int si[160];
    int b = blockIdx.x, tid = threadIdx.x;
    int kk = kptr[0];
    for (int i = tid; i < 160; i += 32) { sv[i] = g_pv[b * 160 + i]; si[i] = g_pi[b * 160 + i]; }
    __syncwarp();
    for (int p = 0; p < kk; p++) {
        float bv = -FLT_MAX; int bi = 0x7fffffff, bs = -1;
        for (int i = tid; i < 160; i += 32) {
            float v = sv[i]; int ix = si[i];
            if (v > bv || (v == bv && ix < bi)) { bv = v; bi = ix; bs = i; }
        }
#pragma unroll
        for (int off = 16; off; off >>= 1) {
            float ov = __shfl_down_sync(0xffffffffu, bv, off);
            int   oi = __shfl_down_sync(0xffffffffu, bi, off);
            int   os = __shfl_down_sync(0xffffffffu, bs, off);
            if (ov > bv || (ov == bv && oi < bi)) { bv = ov; bi = oi; bs = os; }
        }
        bs = __shfl_sync(0xffffffffu, bs, 0);
        if (tid == 0) {
            out[b * kk + p]        = (float)bi;
            out[half + b * kk + p] = bv;
            if (bs >= 0) sv[bs] = -FLT_MAX;
        }
        __syncwarp();
    }
}

// ---------------- launch ----------------------------------------------------
extern "C" void kernel_launch(void* const* d_in, const int* in_sizes, int n_in,
                              void* d_out, int out_size)
{
    const int*   head = (const int*)d_in[0];
    const int*   rel  = (const int*)d_in[1];
    const float* eemb = (const float*)d_in[2];
    const float* remb = (const float*)d_in[3];
    const float* proj = (const float*)d_in[4];
    const int*   kptr = (const int*)d_in[5];

    int B = in_sizes[0];
    int N = in_sizes[2] / DD;
    int CAND = N / 10; if (CAND < 100) CAND = 100;
    int nch = (N + K2CH - 1) / K2CH;

    cudaFuncSetAttribute(k1_entity_bits, cudaFuncAttributeMaxDynamicSharedMemorySize, 200 * 1024);
    cudaFuncSetAttribute(k2_hamming,     cudaFuncAttributeMaxDynamicSharedMemorySize, 80 * 1024);
    cudaFuncSetAttribute(k4_scores,      cudaFuncAttributeMaxDynamicSharedMemorySize, 80 * 1024);

    size_t k1_smem = (32768 + 256 * 65) * sizeof(float);             // 197632
    size_t k2_smem = 8192 + BMAX * 132 * 4 + (size_t)K2CH * 68;      // 76800
    size_t k4_smem = (BMAX * DD + BMAX * 32) * sizeof(float) + 2 * BMAX * sizeof(int);
    size_t k5_smem = SEG * sizeof(float);                            // 25000

    // launch order engineered so ncu's fixed capture (launch idx 3) hits k1
    k0c_zero<<<(BMAX * 129 + 255) / 256, 256>>>();                   // idx 0
    k0a_targets<<<B, 128>>>(head, rel, eemb, remb);                  // idx 1
    k0b_tbits<<<B, 128>>>(proj);                                     // idx 2
    k1_entity_bits<<<148, 256, k1_smem>>>(eemb, proj, N);            // idx 3 (profiled)
    k2_hamming<<<nch, 256, k2_smem>>>(N);
    k3a<<<BMAX, 160>>>(CAND);
    k3b<<<nch, 256>>>(N);
    k3c<<<BMAX, 256>>>(N, nch);
    k4_scores<<<(N + 31) / 32, 256, k4_smem>>>(eemb, N);
    k5a<<<BMAX * 16, 256, k5_smem>>>(N);
    k5b<<<BMAX, 32>>>(kptr, (float*)d_out, out_size / 2);
}

// round 10
// speedup vs baseline: 1.2102x; 1.2102x over previous
#include <cuda_runtime.h>
#include <cstdint>
#include <cfloat>

#define NMAX 100000
#define BMAX 64
#define DD   256
#define TT   4
#define HH   32
#define K2CH 512

// ---------------- scratch (static __device__, no allocation) ----------------
__device__ float         g_targets[BMAX * DD];
__device__ unsigned      g_tbits[BMAX * 4];
__device__ unsigned      g_abits[NMAX * 4];
__device__ unsigned char g_dist_t[(size_t)NMAX * BMAX];   // [n][b]
__device__ unsigned      g_hist[BMAX * 129];
__device__ int           g_dstar[BMAX];
__device__ int           g_r[BMAX];
__device__ int           g_istar[BMAX];
__device__ unsigned      g_cnt[200 * BMAX];               // [chunk][b]
__device__ float         g_scores[(size_t)BMAX * NMAX];   // [b][n]
__device__ float         g_pv[BMAX * 16 * 10];
__device__ int           g_pi[BMAX * 16 * 10];

__device__ __forceinline__ unsigned smem_u32(const void* p) {
    unsigned a;
    asm("{ .reg .u64 t; cvta.to.shared.u64 t, %1; cvt.u32.u64 %0, t; }"
        : "=r"(a) : "l"(p));
    return a;
}
#define FFMA2(acc, a, b) \
    asm("fma.rn.f32x2 %0, %1, %2, %0;" : "+l"(acc) : "l"(a), "l"(b))

// ---------------- K0c: zero histograms (launch idx 0) -----------------------
__global__ void k0c_zero()
{
    int i = blockIdx.x * blockDim.x + threadIdx.x;
    if (i < BMAX * 129) g_hist[i] = 0u;
}

// ---------------- K0a: target embeddings (launch idx 1) ---------------------
__global__ void k0a_targets(const int* __restrict__ head,
                            const int* __restrict__ rel,
                            const float* __restrict__ eemb,
                            const float* __restrict__ remb)
{
    int b = blockIdx.x, tid = threadIdx.x;
    int hh = head[b], rr = rel[b];
    for (int d = tid; d < DD; d += blockDim.x)
        g_targets[b * DD + d] = eemb[(size_t)hh * DD + d] * remb[(size_t)rr * DD + d];
}

// ---------------- K0b: target hash bits (launch idx 2) ----------------------
__global__ void k0b_tbits(const float* __restrict__ proj)
{
    __shared__ float tgt[DD];
    int b = blockIdx.x, tid = threadIdx.x;
    for (int d = tid; d < DD; d += blockDim.x) tgt[d] = g_targets[b * DD + d];
    __syncthreads();
    int t = tid >> 5, lane = tid & 31;
    const float* pp = proj + (size_t)t * DD * HH + lane;
    float acc = 0.f;
#pragma unroll 8
    for (int d = 0; d < DD; d++) acc += tgt[d] * pp[d * HH];
    unsigned w = __ballot_sync(0xffffffffu, acc > 0.f);
    if (lane == 0) g_tbits[b * 4 + t] = w;
}

// ---------------- K1: entity hash bits v3 — column-split, 2 blocks/SM -------
// Block owns 64 proj columns (ch = bid&1). projs [d][64] = 64KB.
// ebuf: R6/R8-proven [d4][128] XOR-swizzled 32-ent tile = 32KB. 96KB -> occ 25%.
// Thread: 8 ents (g=tid>>6) x 1 col (j6=tid&63); acc[4] f32x2.
__global__ __launch_bounds__(256, 2)
void k1_entity_bits(const float* __restrict__ eemb,
                    const float* __restrict__ proj, int N)
{
    extern __shared__ float sm[];
    float* projs = sm;               // 16384 floats (64KB)
    float* ebuf  = sm + 16384;       // 8192 floats (32KB)

    int tid  = threadIdx.x;
    int ch   = blockIdx.x & 1;       // column half
    int j6   = tid & 63;             // local column
    int g    = tid >> 6;             // 0..3 entity group (uniform per warp)
    int w    = tid >> 5, lane = tid & 31;
    int t    = 2 * ch + (w & 1);     // global abits word

    unsigned sb_proj = smem_u32(projs) + (unsigned)(j6 * 4);
    unsigned sb_ebuf = smem_u32(ebuf);

    // stage this block's proj half: global col jj = ch*64 + jl
    for (int i = tid; i < DD * 64; i += 256) {
        int d = i >> 6, jl = i & 63;
        int tt = 2 * ch + (jl >> 5), h = jl & 31;
        projs[d * 64 + jl] = proj[(size_t)tt * DD * HH + d * HH + h];
    }

    int tiles = (N + 31) >> 5;
    int per = (tiles + 147) / 148;
    int pairIdx = blockIdx.x >> 1;   // block pair shares tile range
    int t0 = pairIdx * per, t1 = min(tiles, t0 + per);
    if (t0 >= t1) return;            // whole block exits

    float4 pf[8];
    {
        int base = t0 * 32;
        const float4* src = (const float4*)(eemb + (size_t)base * DD);
        int limit = min(32, N - base) * 64;
#pragma unroll
        for (int k = 0; k < 8; k++) {
            int idx = tid + k * 256;
            pf[k] = (idx < limit) ? src[idx] : make_float4(0.f, 0.f, 0.f, 0.f);
        }
    }
    __syncthreads();                 // projs ready

    for (int tile = t0; tile < t1; tile++) {
        // store prefetched 32-ent tile, XOR-swizzled (identical to R8)
#pragma unroll
        for (int k = 0; k < 8; k++) {
            int idx = tid + k * 256;
            int e = idx >> 6, d4 = idx & 63;
            int blk = (e >> 2) ^ (d4 & 7);
            float* dst = ebuf + d4 * 128 + blk * 4 + (e & 3);
            dst[0]  = pf[k].x;
            dst[32] = pf[k].y;
            dst[64] = pf[k].z;
            dst[96] = pf[k].w;
        }
        __syncthreads();

        if (tile + 1 < t1) {         // next-tile LDGs fly over compute
            int base = (tile + 1) * 32;
            const float4* src = (const float4*)(eemb + (size_t)base * DD);
            int limit = min(32, N - base) * 64;
#pragma unroll
            for (int k = 0; k < 8; k++) {
                int idx = tid + k * 256;
                pf[k] = (idx < limit) ? src[idx] : make_float4(0.f, 0.f, 0.f, 0.f);
            }
        }

        unsigned long long acc[4] = {0, 0, 0, 0};
        for (int d4 = 0; d4 < 64; d4++) {
            int swz = d4 & 7;
            unsigned xb0 = (unsigned)(((g * 2 + 0) ^ swz) << 4);
            unsigned xb1 = (unsigned)(((g * 2 + 1) ^ swz) << 4);
#pragma unroll
            for (int i = 0; i < 4; i++) {
                int d = d4 * 4 + i;
                float p;
                asm("ld.shared.f32 %0, [%1];" : "=f"(p)
                    : "r"(sb_proj + (unsigned)(d * 256)));
                unsigned long long p2;
                asm("mov.b64 %0, {%1, %1};" : "=l"(p2) : "f"(p));
                unsigned eb = sb_ebuf + (unsigned)(d * 128);
                unsigned long long e0, e1;
                asm("ld.shared.v2.b64 {%0,%1}, [%2];" : "=l"(e0), "=l"(e1) : "r"(eb + xb0));
                FFMA2(acc[0], p2, e0); FFMA2(acc[1], p2, e1);
                asm("ld.shared.v2.b64 {%0,%1}, [%2];" : "=l"(e0), "=l"(e1) : "r"(eb + xb1));
                FFMA2(acc[2], p2, e0); FFMA2(acc[3], p2, e1);
            }
        }

        int base = tile * 32;
#pragma unroll
        for (int m = 0; m < 4; m++) {
            float lo, hi;
            asm("mov.b64 {%0,%1}, %2;" : "=f"(lo), "=f"(hi) : "l"(acc[m]));
            unsigned blo = __ballot_sync(0xffffffffu, lo > 0.f);
            unsigned bhi = __ballot_sync(0xffffffffu, hi > 0.f);
            int e = 8 * g + 2 * m;                  // entity of lo; hi = e+1
            if (lane == 0) {
                if (base + e < N)     g_abits[(size_t)(base + e) * 4 + t] = blo;
                if (base + e + 1 < N) g_abits[(size_t)(base + e + 1) * 4 + t] = bhi;
            }
        }
        __syncthreads();             // ebuf reuse
    }
}

// ---------------- K2: hamming + histograms (warp-owns-query, no atomics) ----
__global__ __launch_bounds__(256)
void k2_hamming(int N)
{
    extern __shared__ unsigned char smraw[];
    uint4*         sab   = (uint4*)smraw;                  // 8192
    unsigned*      shist = (unsigned*)(smraw + 8192);      // 33792
    unsigned char* sdist = smraw + 8192 + 33792;           // [512][68]

    int tid = threadIdx.x, w = tid >> 5, lane = tid & 31;
    int base = blockIdx.x * K2CH;
    int cnt  = min(K2CH, N - base);

    for (int i = tid; i < BMAX * 132; i += 256) shist[i] = 0u;
    for (int i = tid; i < cnt * 4; i += 256)
        ((unsigned*)sab)[i] = g_abits[(size_t)base * 4 + i];
    __syncthreads();

    for (int q = w; q < BMAX; q += 8) {
        unsigned t0 = g_tbits[q * 4 + 0], t1 = g_tbits[q * 4 + 1];
        unsigned t2 = g_tbits[q * 4 + 2], t3 = g_tbits[q * 4 + 3];
        unsigned* hrow = shist + q * 132;
        for (int it = 0; it < 16; it++) {
            int i = it * 32 + lane;
            uint4 a = sab[i];
            unsigned d = __popc(a.x ^ t0) + __popc(a.y ^ t1)
                       + __popc(a.z ^ t2) + __popc(a.w ^ t3);
            unsigned d2 = (i < cnt) ? d : 0xffffffffu;
            if (i < cnt) sdist[i * 68 + q] = (unsigned char)d;
            unsigned mask = __match_any_sync(0xffffffffu, d2);
            if ((int)lane == __ffs(mask) - 1 && d2 != 0xffffffffu)
                hrow[d2] = hrow[d2] + __popc(mask);
        }
    }
    __syncthreads();

    for (int idx = tid; idx < K2CH * 16; idx += 256) {
        int i = idx >> 4, c = idx & 15;
        if (i < cnt)
            ((unsigned*)g_dist_t)[((size_t)(base + i)) * 16 + c] =
                *(const unsigned*)(sdist + i * 68 + c * 4);
    }
    for (int i = tid; i < BMAX * 129; i += 256) {
        int q = i / 129, d = i - q * 129;
        unsigned v = shist[q * 132 + d];
        if (v) atomicAdd(&g_hist[i], v);
    }
}

// ---------------- K3a: d*, r via parallel prefix scan -----------------------
__global__ void k3a(int CAND)
{
    __shared__ unsigned s[160];
    int q = blockIdx.x, tid = threadIdx.x;
    unsigned h = (tid < 129) ? g_hist[q * 129 + tid] : 0u;
    s[tid] = h;
    __syncthreads();
#pragma unroll
    for (int off = 1; off < 160; off <<= 1) {
        unsigned v = (tid >= off) ? s[tid - off] : 0u;
        __syncthreads();
        s[tid] += v;
        __syncthreads();
    }
    unsigned cum = s[tid];
    if (tid < 129 && cum >= (unsigned)CAND && cum - h < (unsigned)CAND) {
        g_dstar[q] = tid;
        g_r[q] = CAND - (int)(cum - h);
    }
}

// ---------------- K3b: per-chunk count of dist == d* ------------------------
__global__ __launch_bounds__(256) void k3b(int N)
{
    __shared__ unsigned char sd[K2CH * 68];
    __shared__ int sds[BMAX];
    int tid = threadIdx.x, w = tid >> 5, lane = tid & 31;
    int base = blockIdx.x * K2CH, cnt = min(K2CH, N - base);
    if (tid < BMAX) sds[tid] = g_dstar[tid];
    for (int idx = tid; idx < cnt * 16; idx += 256) {
        int i = idx >> 4, c = idx & 15;
        *(unsigned*)(sd + i * 68 + c * 4) =
            ((const unsigned*)g_dist_t)[((size_t)(base + i)) * 16 + c];
    }
    __syncthreads();
    for (int q = w; q < BMAX; q += 8) {
        int ds = sds[q]; unsigned c = 0;
        for (int it = 0; it < 16; it++) {
            int i = it * 32 + lane;
            int f = (i < cnt) && (sd[i * 68 + q] == ds);
            c += __popc(__ballot_sync(0xffffffffu, f));
        }
        if (lane == 0) g_cnt[blockIdx.x * BMAX + q] = c;
    }
}

// ---------------- K3c: index cutoff I* --------------------------------------
__global__ void k3c(int N, int nch)
{
    __shared__ unsigned scnt[256];
    __shared__ int s_c, s_rem;
    __shared__ unsigned char fl[K2CH];
    int q = blockIdx.x, tid = threadIdx.x;
    scnt[tid] = (tid < nch) ? g_cnt[tid * BMAX + q] : 0u;
    __syncthreads();
    if (tid == 0) {
        int r = g_r[q]; unsigned cum = 0; int c = 0;
        for (;; c++) {
            unsigned h = scnt[c];
            if (cum + h >= (unsigned)r) { s_c = c; s_rem = r - (int)cum; break; }
            cum += h;
        }
    }
    __syncthreads();
    int base = s_c * K2CH, ds = g_dstar[q];
    for (int i = tid; i < K2CH; i += blockDim.x) {
        int n = base + i;
        fl[i] = (n < N && g_dist_t[(size_t)n * BMAX + q] == (unsigned char)ds) ? 1 : 0;
    }
    __syncthreads();
    if (tid == 0) {
        int need = s_rem, c2 = 0, i = 0;
        for (;; i++) { c2 += fl[i]; if (c2 == need) break; }
        g_istar[q] = base + i;
    }
}

// ---------------- K4: candidate scores (gather; dense [B][N] fill) ----------
__global__ __launch_bounds__(256)
void k4_scores(const float* __restrict__ eemb, int N)
{
    extern __shared__ float sm4[];
    float* st   = sm4;                       // targets 64*256
    float* tile = sm4 + BMAX * DD;           // [64][32]
    int*   ds   = (int*)(tile + BMAX * 32);
    int*   is_  = ds + BMAX;

    int tid = threadIdx.x;
    for (int i = tid; i < BMAX * DD; i += blockDim.x) st[i] = g_targets[i];
    if (tid < BMAX) { ds[tid] = g_dstar[tid]; is_[tid] = g_istar[tid]; }
    for (int i = tid; i < BMAX * 32; i += blockDim.x) tile[i] = -FLT_MAX;
    __syncthreads();

    int base = blockIdx.x * 32;
    int w = tid >> 5, lane = tid & 31;

    for (int e = 0; e < 4; e++) {
        int i = w * 4 + e;
        int n = base + i;
        if (n >= N) continue;  // uniform per warp
        float4 r0 = *(const float4*)(eemb + (size_t)n * DD + lane * 8);
        float4 r1 = *(const float4*)(eemb + (size_t)n * DD + lane * 8 + 4);
        unsigned char d0 = g_dist_t[(size_t)n * BMAX + lane];
        unsigned char d1 = g_dist_t[(size_t)n * BMAX + 32 + lane];
        int b0 = lane, b1 = lane + 32;
        bool f0 = (d0 < ds[b0]) || (d0 == ds[b0] && n <= is_[b0]);
        bool f1 = (d1 < ds[b1]) || (d1 == ds[b1] && n <= is_[b1]);
        unsigned m0 = __ballot_sync(0xffffffffu, f0);
        unsigned m1 = __ballot_sync(0xffffffffu, f1);

        while (m0) {
            int b = __ffs(m0) - 1; m0 &= m0 - 1;
            const float4* tp = (const float4*)(st + b * DD + lane * 8);
            float4 t0 = tp[0], t1 = tp[1];
            float s = r0.x * t0.x + r0.y * t0.y + r0.z * t0.z + r0.w * t0.w
                    + r1.x * t1.x + r1.y * t1.y + r1.z * t1.z + r1.w * t1.w;
#pragma unroll
            for (int off = 16; off; off >>= 1) s += __shfl_xor_sync(0xffffffffu, s, off);
            if (lane == 0) tile[b * 32 + i] = s;
        }
        while (m1) {
            int b = 32 + __ffs(m1) - 1; m1 &= m1 - 1;
            const float4* tp = (const float4*)(st + b * DD + lane * 8);
            float4 t0 = tp[0], t1 = tp[1];
            float s = r0.x * t0.x + r0.y * t0.y + r0.z * t0.z + r0.w * t0.w
                    + r1.x * t1.x + r1.y * t1.y + r1.z * t1.z + r1.w * t1.w;
#pragma unroll
            for (int off = 16; off; off >>= 1) s += __shfl_xor_sync(0xffffffffu, s, off);
            if (lane == 0) tile[b * 32 + i] = s;
        }
    }
    __syncthreads();
    for (int idx = tid; idx < BMAX * 32; idx += blockDim.x) {
        int bb = idx >> 5, i = idx & 31;
        int n = base + i;
        if (n < N) g_scores[(size_t)bb * N + n] = tile[idx];
    }
}

// ---------------- K5a: per-segment top-10 in smem ---------------------------
#define SEG 6250
__global__ __launch_bounds__(256) void k5a(int N)
{
    extern __shared__ float sv[];            // SEG floats
    __shared__ float wv[8]; __shared__ int wi[8];
    int b = blockIdx.x >> 4, s = blockIdx.x & 15;
    int tid = threadIdx.x, w = tid >> 5, lane = tid & 31;
    int base = s * SEG;
    const float* src = g_scores + (size_t)b * N;
    for (int i = tid; i < SEG; i += 256)
        sv[i] = (base + i < N) ? src[base + i] : -FLT_MAX;
    __syncthreads();

    for (int p = 0; p < 10; p++) {
        float bv = -FLT_MAX; int bi = 1 << 30;
        for (int i = tid; i < SEG; i += 256) {
            float v = sv[i];
            if (v > bv) { bv = v; bi = i; }
        }
#pragma unroll
        for (int off = 16; off; off >>= 1) {
            float ov = __shfl_down_sync(0xffffffffu, bv, off);
            int   oi = __shfl_down_sync(0xffffffffu, bi, off);
            if (ov > bv || (ov == bv && oi < bi)) { bv = ov; bi = oi; }
        }
        if (lane == 0) { wv[w] = bv; wi[w] = bi; }
        __syncthreads();
        if (tid == 0) {
            float fv = wv[0]; int fi = wi[0];
            for (int x = 1; x < 8; x++)
                if (wv[x] > fv || (wv[x] == fv && wi[x] < fi)) { fv = wv[x]; fi = wi[x]; }
            g_pv[blockIdx.x * 10 + p] = fv;
            g_pi[blockIdx.x * 10 + p] = base + ((fi < SEG) ? fi : 0);
            if (fi < SEG) sv[fi] = -FLT_MAX;
        }
        __syncthreads();
    }
}

// ---------------- K5b: merge 16x10 -> top-k (one warp per query) ------------
__global__ void k5b(const int* __restrict__ kptr, float* __restrict__ out, int half)
{
    __shared__ float sv[160]; __shared__ int si[160];
    int b = blockIdx.x, tid = threadIdx.x;
    int kk = kptr[0];
    for (int i = tid; i < 160; i += 32) { sv[i] = g_pv[b * 160 + i]; si[i] = g_pi[b * 160 + i]; }
    __syncwarp();
    for (int p = 0; p < kk; p++) {
        float bv = -FLT_MAX; int bi = 0x7fffffff, bs = -1;
        for (int i = tid; i < 160; i += 32) {
            float v = sv[i]; int ix = si[i];
            if (v > bv || (v == bv && ix < bi)) { bv = v; bi = ix; bs = i; }
        }
#pragma unroll
        for (int off = 16; off; off >>= 1) {
            float ov = __shfl_down_sync(0xffffffffu, bv, off);
            int   oi = __shfl_down_sync(0xffffffffu, bi, off);
            int   os = __shfl_down_sync(0xffffffffu, bs, off);
            if (ov > bv || (ov == bv && oi < bi)) { bv = ov; bi = oi; bs = os; }
        }
        bs = __shfl_sync(0xffffffffu, bs, 0);
        if (tid == 0) {
            out[b * kk + p]        = (float)bi;
            out[half + b * kk + p] = bv;
            if (bs >= 0) sv[bs] = -FLT_MAX;
        }
        __syncwarp();
    }
}

// ---------------- launch ----------------------------------------------------
extern "C" void kernel_launch(void* const* d_in, const int* in_sizes, int n_in,
                              void* d_out, int out_size)
{
    const int*   head = (const int*)d_in[0];
    const int*   rel  = (const int*)d_in[1];
    const float* eemb = (const float*)d_in[2];
    const float* remb = (const float*)d_in[3];
    const float* proj = (const float*)d_in[4];
    const int*   kptr = (const int*)d_in[5];

    int B = in_sizes[0];
    int N = in_sizes[2] / DD;
    int CAND = N / 10; if (CAND < 100) CAND = 100;
    int nch = (N + K2CH - 1) / K2CH;

    cudaFuncSetAttribute(k1_entity_bits, cudaFuncAttributeMaxDynamicSharedMemorySize, 100 * 1024);
    cudaFuncSetAttribute(k2_hamming,     cudaFuncAttributeMaxDynamicSharedMemorySize, 80 * 1024);
    cudaFuncSetAttribute(k4_scores,      cudaFuncAttributeMaxDynamicSharedMemorySize, 80 * 1024);

    size_t k1_smem = (16384 + 8192) * sizeof(float);                 // 98304
    size_t k2_smem = 8192 + BMAX * 132 * 4 + (size_t)K2CH * 68;      // 76800
    size_t k4_smem = (BMAX * DD + BMAX * 32) * sizeof(float) + 2 * BMAX * sizeof(int);
    size_t k5_smem = SEG * sizeof(float);                            // 25000

    // launch order engineered so ncu's fixed capture (launch idx 3) hits k1
    k0c_zero<<<(BMAX * 129 + 255) / 256, 256>>>();                   // idx 0
    k0a_targets<<<B, 128>>>(head, rel, eemb, remb);                  // idx 1
    k0b_tbits<<<B, 128>>>(proj);                                     // idx 2
    k1_entity_bits<<<296, 256, k1_smem>>>(eemb, proj, N);            // idx 3 (profiled)
    k2_hamming<<<nch, 256, k2_smem>>>(N);
    k3a<<<BMAX, 160>>>(CAND);
    k3b<<<nch, 256>>>(N);
    k3c<<<BMAX, 256>>>(N, nch);
    k4_scores<<<(N + 31) / 32, 256, k4_smem>>>(eemb, N);
    k5a<<<BMAX * 16, 256, k5_smem>>>(N);
    k5b<<<BMAX, 32>>>(kptr, (float*)d_out, out_size / 2);
}

// round 11
// speedup vs baseline: 1.3220x; 1.0923x over previous
#include <cuda_runtime.h>
#include <cstdint>
#include <cfloat>

#define NMAX 100000
#define BMAX 64
#define DD   256
#define TT   4
#define HH   32
#define K2CH 512

// ---------------- scratch (static __device__, no allocation) ----------------
__device__ float         g_targets[BMAX * DD];
__device__ unsigned      g_tbits[BMAX * 4];
__device__ unsigned      g_abits[NMAX * 4];
__device__ unsigned char g_dist_t[(size_t)NMAX * BMAX];   // [n][b]
__device__ unsigned      g_hist[BMAX * 129];
__device__ int           g_dstar[BMAX];
__device__ int           g_r[BMAX];
__device__ int           g_istar[BMAX];
__device__ unsigned      g_cnt[200 * BMAX];               // [chunk][b]
__device__ float         g_scores[(size_t)BMAX * NMAX];   // [b][n]
__device__ float         g_pv[BMAX * 16 * 10];
__device__ int           g_pi[BMAX * 16 * 10];

__device__ __forceinline__ unsigned smem_u32(const void* p) {
    unsigned a;
    asm("{ .reg .u64 t; cvta.to.shared.u64 t, %1; cvt.u32.u64 %0, t; }"
        : "=r"(a) : "l"(p));
    return a;
}
#define FFMA2(acc, a, b) \
    asm("fma.rn.f32x2 %0, %1, %2, %0;" : "+l"(acc) : "l"(a), "l"(b))

// ---------------- K0m: targets + zero hist (launch idx 0) -------------------
__global__ void k0m_targets(const int* __restrict__ head,
                            const int* __restrict__ rel,
                            const float* __restrict__ eemb,
                            const float* __restrict__ remb)
{
    int b = blockIdx.x, tid = threadIdx.x;
    int hh = head[b], rr = rel[b];
    for (int d = tid; d < DD; d += blockDim.x)
        g_targets[b * DD + d] = eemb[(size_t)hh * DD + d] * remb[(size_t)rr * DD + d];
    for (int i = tid; i < 129; i += blockDim.x) g_hist[b * 129 + i] = 0u;
}

// ---------------- K0b: target hash bits (launch idx 1) ----------------------
__global__ void k0b_tbits(const float* __restrict__ proj)
{
    __shared__ float tgt[DD];
    int b = blockIdx.x, tid = threadIdx.x;
    for (int d = tid; d < DD; d += blockDim.x) tgt[d] = g_targets[b * DD + d];
    __syncthreads();
    int t = tid >> 5, lane = tid & 31;
    const float* pp = proj + (size_t)t * DD * HH + lane;
    float acc = 0.f;
#pragma unroll 8
    for (int d = 0; d < DD; d++) acc += tgt[d] * pp[d * HH];
    unsigned w = __ballot_sync(0xffffffffu, acc > 0.f);
    if (lane == 0) g_tbits[b * 4 + t] = w;
}

// ---------------- K1: entity hash bits (R8 form — best known) ---------------
__global__ __launch_bounds__(256, 1)
void k1_entity_bits(const float* __restrict__ eemb,
                    const float* __restrict__ proj, int N)
{
    extern __shared__ float sm[];
    float* projs = sm;               // 32768 floats
    float* ebuf  = sm + 32768;       // 8192 floats

    int tid  = threadIdx.x;
    int j    = tid & 127;
    int g    = tid >> 7;             // uniform per warp
    int w    = tid >> 5, lane = tid & 31;
    int t    = w & 3;

    unsigned sb_proj = smem_u32(projs) + (unsigned)(j * 4);
    unsigned sb_ebuf = smem_u32(ebuf);

    for (int i = tid; i < TT * DD * HH; i += 256) {
        int tt = i >> 13, d = (i >> 5) & 255, h = i & 31;
        projs[d * 128 + tt * 32 + h] = proj[i];
    }

    int tiles = (N + 31) >> 5;
    int per = (tiles + gridDim.x - 1) / gridDim.x;
    int t0 = blockIdx.x * per, t1 = min(tiles, t0 + per);
    if (t0 >= t1) return;

    float4 pf[8];
    {
        int base = t0 * 32;
        const float4* src = (const float4*)(eemb + (size_t)base * DD);
        int limit = min(32, N - base) * 64;
#pragma unroll
        for (int k = 0; k < 8; k++) {
            int idx = tid + k * 256;
            pf[k] = (idx < limit) ? src[idx] : make_float4(0.f, 0.f, 0.f, 0.f);
        }
    }
    __syncthreads();

    for (int tile = t0; tile < t1; tile++) {
#pragma unroll
        for (int k = 0; k < 8; k++) {
            int idx = tid + k * 256;
            int e = idx >> 6, d4 = idx & 63;
            int blk = (e >> 2) ^ (d4 & 7);
            float* dst = ebuf + d4 * 128 + blk * 4 + (e & 3);
            dst[0]  = pf[k].x;
            dst[32] = pf[k].y;
            dst[64] = pf[k].z;
            dst[96] = pf[k].w;
        }
        __syncthreads();

        if (tile + 1 < t1) {
            int base = (tile + 1) * 32;
            const float4* src = (const float4*)(eemb + (size_t)base * DD);
            int limit = min(32, N - base) * 64;
#pragma unroll
            for (int k = 0; k < 8; k++) {
                int idx = tid + k * 256;
                pf[k] = (idx < limit) ? src[idx] : make_float4(0.f, 0.f, 0.f, 0.f);
            }
        }

        unsigned long long acc[8] = {0, 0, 0, 0, 0, 0, 0, 0};
        for (int d4 = 0; d4 < 64; d4++) {
            int swz = d4 & 7;
            unsigned xb0 = (unsigned)(((g * 4 + 0) ^ swz) << 4);
            unsigned xb1 = (unsigned)(((g * 4 + 1) ^ swz) << 4);
            unsigned xb2 = (unsigned)(((g * 4 + 2) ^ swz) << 4);
            unsigned xb3 = (unsigned)(((g * 4 + 3) ^ swz) << 4);
#pragma unroll
            for (int i = 0; i < 4; i++) {
                int d = d4 * 4 + i;
                float p;
                asm("ld.shared.f32 %0, [%1];" : "=f"(p)
                    : "r"(sb_proj + (unsigned)(d * 512)));
                unsigned long long p2;
                asm("mov.b64 %0, {%1, %1};" : "=l"(p2) : "f"(p));
                unsigned eb = sb_ebuf + (unsigned)(d * 128);
                unsigned long long e0, e1;
                asm("ld.shared.v2.b64 {%0,%1}, [%2];" : "=l"(e0), "=l"(e1) : "r"(eb + xb0));
                FFMA2(acc[0], p2, e0); FFMA2(acc[1], p2, e1);
                asm("ld.shared.v2.b64 {%0,%1}, [%2];" : "=l"(e0), "=l"(e1) : "r"(eb + xb1));
                FFMA2(acc[2], p2, e0); FFMA2(acc[3], p2, e1);
                asm("ld.shared.v2.b64 {%0,%1}, [%2];" : "=l"(e0), "=l"(e1) : "r"(eb + xb2));
                FFMA2(acc[4], p2, e0); FFMA2(acc[5], p2, e1);
                asm("ld.shared.v2.b64 {%0,%1}, [%2];" : "=l"(e0), "=l"(e1) : "r"(eb + xb3));
                FFMA2(acc[6], p2, e0); FFMA2(acc[7], p2, e1);
            }
        }

        int base = tile * 32;
#pragma unroll
        for (int m = 0; m < 8; m++) {
            float lo, hi;
            asm("mov.b64 {%0,%1}, %2;" : "=f"(lo), "=f"(hi) : "l"(acc[m]));
            unsigned blo = __ballot_sync(0xffffffffu, lo > 0.f);
            unsigned bhi = __ballot_sync(0xffffffffu, hi > 0.f);
            int e0 = g * 16 + 2 * m;
            if (lane == 0) {
                if (base + e0 < N)     g_abits[(size_t)(base + e0) * 4 + t] = blo;
                if (base + e0 + 1 < N) g_abits[(size_t)(base + e0 + 1) * 4 + t] = bhi;
            }
        }
        __syncthreads();
    }
}

// ---------------- K2: hamming + histograms (launch idx 3 — profiled) --------
__global__ __launch_bounds__(256)
void k2_hamming(int N)
{
    extern __shared__ unsigned char smraw[];
    uint4*         sab   = (uint4*)smraw;                  // 8192
    unsigned*      shist = (unsigned*)(smraw + 8192);      // 33792
    unsigned char* sdist = smraw + 8192 + 33792;           // [512][68]

    int tid = threadIdx.x, w = tid >> 5, lane = tid & 31;
    int base = blockIdx.x * K2CH;
    int cnt  = min(K2CH, N - base);

    for (int i = tid; i < BMAX * 132; i += 256) shist[i] = 0u;
    for (int i = tid; i < cnt * 4; i += 256)
        ((unsigned*)sab)[i] = g_abits[(size_t)base * 4 + i];
    __syncthreads();

    for (int q = w; q < BMAX; q += 8) {
        unsigned t0 = g_tbits[q * 4 + 0], t1 = g_tbits[q * 4 + 1];
        unsigned t2 = g_tbits[q * 4 + 2], t3 = g_tbits[q * 4 + 3];
        unsigned* hrow = shist + q * 132;
        for (int it = 0; it < 16; it++) {
            int i = it * 32 + lane;
            uint4 a = sab[i];
            unsigned d = __popc(a.x ^ t0) + __popc(a.y ^ t1)
                       + __popc(a.z ^ t2) + __popc(a.w ^ t3);
            unsigned d2 = (i < cnt) ? d : 0xffffffffu;
            if (i < cnt) sdist[i * 68 + q] = (unsigned char)d;
            unsigned mask = __match_any_sync(0xffffffffu, d2);
            if ((int)lane == __ffs(mask) - 1 && d2 != 0xffffffffu)
                hrow[d2] = hrow[d2] + __popc(mask);
        }
    }
    __syncthreads();

    for (int idx = tid; idx < K2CH * 16; idx += 256) {
        int i = idx >> 4, c = idx & 15;
        if (i < cnt)
            ((unsigned*)g_dist_t)[((size_t)(base + i)) * 16 + c] =
                *(const unsigned*)(sdist + i * 68 + c * 4);
    }
    for (int i = tid; i < BMAX * 129; i += 256) {
        int q = i / 129, d = i - q * 129;
        unsigned v = shist[q * 132 + d];
        if (v) atomicAdd(&g_hist[i], v);
    }
}

// ---------------- K3a: d*, r via parallel prefix scan -----------------------
__global__ void k3a(int CAND)
{
    __shared__ unsigned s[160];
    int q = blockIdx.x, tid = threadIdx.x;
    unsigned h = (tid < 129) ? g_hist[q * 129 + tid] : 0u;
    s[tid] = h;
    __syncthreads();
#pragma unroll
    for (int off = 1; off < 160; off <<= 1) {
        unsigned v = (tid >= off) ? s[tid - off] : 0u;
        __syncthreads();
        s[tid] += v;
        __syncthreads();
    }
    unsigned cum = s[tid];
    if (tid < 129 && cum >= (unsigned)CAND && cum - h < (unsigned)CAND) {
        g_dstar[q] = tid;
        g_r[q] = CAND - (int)(cum - h);
    }
}

// ---------------- K3b: per-chunk count of dist == d* ------------------------
__global__ __launch_bounds__(256) void k3b(int N)
{
    __shared__ unsigned char sd[K2CH * 68];
    __shared__ int sds[BMAX];
    int tid = threadIdx.x, w = tid >> 5, lane = tid & 31;
    int base = blockIdx.x * K2CH, cnt = min(K2CH, N - base);
    if (tid < BMAX) sds[tid] = g_dstar[tid];
    for (int idx = tid; idx < cnt * 16; idx += 256) {
        int i = idx >> 4, c = idx & 15;
        *(unsigned*)(sd + i * 68 + c * 4) =
            ((const unsigned*)g_dist_t)[((size_t)(base + i)) * 16 + c];
    }
    __syncthreads();
    for (int q = w; q < BMAX; q += 8) {
        int ds = sds[q]; unsigned c = 0;
        for (int it = 0; it < 16; it++) {
            int i = it * 32 + lane;
            int f = (i < cnt) && (sd[i * 68 + q] == ds);
            c += __popc(__ballot_sync(0xffffffffu, f));
        }
        if (lane == 0) g_cnt[blockIdx.x * BMAX + q] = c;
    }
}

// ---------------- K3c: index cutoff I* --------------------------------------
__global__ void k3c(int N, int nch)
{
    __shared__ unsigned scnt[256];
    __shared__ int s_c, s_rem;
    __shared__ unsigned char fl[K2CH];
    int q = blockIdx.x, tid = threadIdx.x;
    scnt[tid] = (tid < nch) ? g_cnt[tid * BMAX + q] : 0u;
    __syncthreads();
    if (tid == 0) {
        int r = g_r[q]; unsigned cum = 0; int c = 0;
        for (;; c++) {
            unsigned h = scnt[c];
            if (cum + h >= (unsigned)r) { s_c = c; s_rem = r - (int)cum; break; }
            cum += h;
        }
    }
    __syncthreads();
    int base = s_c * K2CH, ds = g_dstar[q];
    for (int i = tid; i < K2CH; i += blockDim.x) {
        int n = base + i;
        fl[i] = (n < N && g_dist_t[(size_t)n * BMAX + q] == (unsigned char)ds) ? 1 : 0;
    }
    __syncthreads();
    if (tid == 0) {
        int need = s_rem, c2 = 0, i = 0;
        for (;; i++) { c2 += fl[i]; if (c2 == need) break; }
        g_istar[q] = base + i;
    }
}

// ---------------- K4: candidate scores — persistent (stage targets once) ----
__global__ __launch_bounds__(256)
void k4_scores(const float* __restrict__ eemb, int N)
{
    extern __shared__ float sm4[];
    float* st   = sm4;                       // targets 64*256
    float* tile = sm4 + BMAX * DD;           // [64][32]
    int*   ds   = (int*)(tile + BMAX * 32);
    int*   is_  = ds + BMAX;

    int tid = threadIdx.x;
    for (int i = tid; i < BMAX * DD; i += blockDim.x) st[i] = g_targets[i];
    if (tid < BMAX) { ds[tid] = g_dstar[tid]; is_[tid] = g_istar[tid]; }
    __syncthreads();

    int w = tid >> 5, lane = tid & 31;
    int ntiles = (N + 31) >> 5;

    for (int tb = blockIdx.x; tb < ntiles; tb += gridDim.x) {
        int base = tb * 32;
        for (int i = tid; i < BMAX * 32; i += blockDim.x) tile[i] = -FLT_MAX;
        __syncthreads();

        for (int e = 0; e < 4; e++) {
            int i = w * 4 + e;
            int n = base + i;
            if (n >= N) continue;  // uniform per warp
            float4 r0 = *(const float4*)(eemb + (size_t)n * DD + lane * 8);
            float4 r1 = *(const float4*)(eemb + (size_t)n * DD + lane * 8 + 4);
            unsigned char d0 = g_dist_t[(size_t)n * BMAX + lane];
            unsigned char d1 = g_dist_t[(size_t)n * BMAX + 32 + lane];
            int b0 = lane, b1 = lane + 32;
            bool f0 = (d0 < ds[b0]) || (d0 == ds[b0] && n <= is_[b0]);
            bool f1 = (d1 < ds[b1]) || (d1 == ds[b1] && n <= is_[b1]);
            unsigned m0 = __ballot_sync(0xffffffffu, f0);
            unsigned m1 = __ballot_sync(0xffffffffu, f1);

            while (m0) {
                int b = __ffs(m0) - 1; m0 &= m0 - 1;
                const float4* tp = (const float4*)(st + b * DD + lane * 8);
                float4 t0 = tp[0], t1 = tp[1];
                float s = r0.x * t0.x + r0.y * t0.y + r0.z * t0.z + r0.w * t0.w
                        + r1.x * t1.x + r1.y * t1.y + r1.z * t1.z + r1.w * t1.w;
#pragma unroll
                for (int off = 16; off; off >>= 1) s += __shfl_xor_sync(0xffffffffu, s, off);
                if (lane == 0) tile[b * 32 + i] = s;
            }
            while (m1) {
                int b = 32 + __ffs(m1) - 1; m1 &= m1 - 1;
                const float4* tp = (const float4*)(st + b * DD + lane * 8);
                float4 t0 = tp[0], t1 = tp[1];
                float s = r0.x * t0.x + r0.y * t0.y + r0.z * t0.z + r0.w * t0.w
                        + r1.x * t1.x + r1.y * t1.y + r1.z * t1.z + r1.w * t1.w;
#pragma unroll
                for (int off = 16; off; off >>= 1) s += __shfl_xor_sync(0xffffffffu, s, off);
                if (lane == 0) tile[b * 32 + i] = s;
            }
        }
        __syncthreads();
        for (int idx = tid; idx < BMAX * 32; idx += blockDim.x) {
            int bb = idx >> 5, i = idx & 31;
            int n = base + i;
            if (n < N) g_scores[(size_t)bb * N + n] = tile[idx];
        }
        __syncthreads();
    }
}

// ---------------- K5a: per-segment top-10 in smem ---------------------------
#define SEG 6250
__global__ __launch_bounds__(256) void k5a(int N)
{
    extern __shared__ float sv[];            // SEG floats
    __shared__ float wv[8]; __shared__ int wi[8];
    int b = blockIdx.x >> 4, s = blockIdx.x & 15;
    int tid = threadIdx.x, w = tid >> 5, lane = tid & 31;
    int base = s * SEG;
    const float* src = g_scores + (size_t)b * N;
    for (int i = tid; i < SEG; i += 256)
        sv[i] = (base + i < N) ? src[base + i] : -FLT_MAX;
    __syncthreads();

    for (int p = 0; p < 10; p++) {
        float bv = -FLT_MAX; int bi = 1 << 30;
        for (int i = tid; i < SEG; i += 256) {
            float v = sv[i];
            if (v > bv) { bv = v; bi = i; }
        }
#pragma unroll
        for (int off = 16; off; off >>= 1) {
            float ov = __shfl_down_sync(0xffffffffu, bv, off);
            int   oi = __shfl_down_sync(0xffffffffu, bi, off);
            if (ov > bv || (ov == bv && oi < bi)) { bv = ov; bi = oi; }
        }
        if (lane == 0) { wv[w] = bv; wi[w] = bi; }
        __syncthreads();
        if (tid == 0) {
            float fv = wv[0]; int fi = wi[0];
            for (int x = 1; x < 8; x++)
                if (wv[x] > fv || (wv[x] == fv && wi[x] < fi)) { fv = wv[x]; fi = wi[x]; }
            g_pv[blockIdx.x * 10 + p] = fv;
            g_pi[blockIdx.x * 10 + p] = base + ((fi < SEG) ? fi : 0);
            if (fi < SEG) sv[fi] = -FLT_MAX;
        }
        __syncthreads();
    }
}

// ---------------- K5b: merge 16x10 -> top-k (one warp per query) ------------
__global__ void k5b(const int* __restrict__ kptr, float* __restrict__ out, int half)
{
    __shared__ float sv[160]; __shared__ int si[160];
    int b = blockIdx.x, tid = threadIdx.x;
    int kk = kptr[0];
    for (int i = tid; i < 160; i += 32) { sv[i] = g_pv[b * 160 + i]; si[i] = g_pi[b * 160 + i]; }
    __syncwarp();
    for (int p = 0; p < kk; p++) {
        float bv = -FLT_MAX; int bi = 0x7fffffff, bs = -1;
        for (int i = tid; i < 160; i += 32) {
            float v = sv[i]; int ix = si[i];
            if (v > bv || (v == bv && ix < bi)) { bv = v; bi = ix; bs = i; }
        }
#pragma unroll
        for (int off = 16; off; off >>= 1) {
            float ov = __shfl_down_sync(0xffffffffu, bv, off);
            int   oi = __shfl_down_sync(0xffffffffu, bi, off);
            int   os = __shfl_down_sync(0xffffffffu, bs, off);
            if (ov > bv || (ov == bv && oi < bi)) { bv = ov; bi = oi; bs = os; }
        }
        bs = __shfl_sync(0xffffffffu, bs, 0);
        if (tid == 0) {
            out[b * kk + p]        = (float)bi;
            out[half + b * kk + p] = bv;
            if (bs >= 0) sv[bs] = -FLT_MAX;
        }
        __syncwarp();
    }
}

// ---------------- launch ----------------------------------------------------
extern "C" void kernel_launch(void* const* d_in, const int* in_sizes, int n_in,
                              void* d_out, int out_size)
{
    const int*   head = (const int*)d_in[0];
    const int*   rel  = (const int*)d_in[1];
    const float* eemb = (const float*)d_in[2];
    const float* remb = (const float*)d_in[3];
    const float* proj = (const float*)d_in[4];
    const int*   kptr = (const int*)d_in[5];

    int B = in_sizes[0];
    int N = in_sizes[2] / DD;
    int CAND = N / 10; if (CAND < 100) CAND = 100;
    int nch = (N + K2CH - 1) / K2CH;

    cudaFuncSetAttribute(k1_entity_bits, cudaFuncAttributeMaxDynamicSharedMemorySize, 164 * 1024);
    cudaFuncSetAttribute(k2_hamming,     cudaFuncAttributeMaxDynamicSharedMemorySize, 80 * 1024);
    cudaFuncSetAttribute(k4_scores,      cudaFuncAttributeMaxDynamicSharedMemorySize, 80 * 1024);

    size_t k1_smem = (32768 + 8192) * sizeof(float);                 // 163840
    size_t k2_smem = 8192 + BMAX * 132 * 4 + (size_t)K2CH * 68;      // 76800
    size_t k4_smem = (BMAX * DD + BMAX * 32) * sizeof(float) + 2 * BMAX * sizeof(int);
    size_t k5_smem = SEG * sizeof(float);                            // 25000

    // launch order: idx 3 = k2 (profiled this round)
    k0m_targets<<<B, 128>>>(head, rel, eemb, remb);                  // idx 0
    k0b_tbits<<<B, 128>>>(proj);                                     // idx 1
    k1_entity_bits<<<148, 256, k1_smem>>>(eemb, proj, N);            // idx 2
    k2_hamming<<<nch, 256, k2_smem>>>(N);                            // idx 3 (profiled)
    k3a<<<BMAX, 160>>>(CAND);
    k3b<<<nch, 256>>>(N);
    k3c<<<BMAX, 256>>>(N, nch);
    k4_scores<<<444, 256, k4_smem>>>(eemb, N);
    k5a<<<BMAX * 16, 256, k5_smem>>>(N);
    k5b<<<BMAX, 32>>>(kptr, (float*)d_out, out_size / 2);
}

// round 14
// speedup vs baseline: 1.3510x; 1.0220x over previous
#include <cuda_runtime.h>
#include <cstdint>
#include <cfloat>

#define NMAX 100000
#define BMAX 64
#define DD   256
#define TT   4
#define HH   32
#define K2CH 256   // k2 chunk (4 blocks/SM)
#define K3CH 512   // k3b/k3c chunk

// ---------------- scratch (static __device__, no allocation) ----------------
__device__ float         g_targets[BMAX * DD];
__device__ unsigned      g_tbits[BMAX * 4];
__device__ unsigned      g_abits[NMAX * 4];
__device__ unsigned char g_dist_t[(size_t)NMAX * BMAX];   // [n][b]
__device__ unsigned      g_hist[BMAX * 129];
__device__ int           g_dstar[BMAX];
__device__ int           g_r[BMAX];
__device__ int           g_istar[BMAX];
__device__ unsigned      g_cnt[200 * BMAX];               // [chunk512][b]
__device__ float         g_scores[(size_t)BMAX * NMAX];   // [b][n]
__device__ float         g_pv[BMAX * 16 * 10];
__device__ int           g_pi[BMAX * 16 * 10];

__device__ __forceinline__ unsigned smem_u32(const void* p) {
    unsigned a;
    asm("{ .reg .u64 t; cvta.to.shared.u64 t, %1; cvt.u32.u64 %0, t; }"
        : "=r"(a) : "l"(p));
    return a;
}
#define FFMA2(acc, a, b) \
    asm("fma.rn.f32x2 %0, %1, %2, %0;" : "+l"(acc) : "l"(a), "l"(b))

// ---------------- K0m: targets + zero hist (launch idx 0) -------------------
__global__ void k0m_targets(const int* __restrict__ head,
                            const int* __restrict__ rel,
                            const float* __restrict__ eemb,
                            const float* __restrict__ remb)
{
    int b = blockIdx.x, tid = threadIdx.x;
    int hh = head[b], rr = rel[b];
    for (int d = tid; d < DD; d += blockDim.x)
        g_targets[b * DD + d] = eemb[(size_t)hh * DD + d] * remb[(size_t)rr * DD + d];
    for (int i = tid; i < 129; i += blockDim.x) g_hist[b * 129 + i] = 0u;
}

// ---------------- K0b: target hash bits (launch idx 1) ----------------------
__global__ void k0b_tbits(const float* __restrict__ proj)
{
    __shared__ float tgt[DD];
    int b = blockIdx.x, tid = threadIdx.x;
    for (int d = tid; d < DD; d += blockDim.x) tgt[d] = g_targets[b * DD + d];
    __syncthreads();
    int t = tid >> 5, lane = tid & 31;
    const float* pp = proj + (size_t)t * DD * HH + lane;
    float acc = 0.f;
#pragma unroll 8
    for (int d = 0; d < DD; d++) acc += tgt[d] * pp[d * HH];
    unsigned w = __ballot_sync(0xffffffffu, acc > 0.f);
    if (lane == 0) g_tbits[b * 4 + t] = w;
}

// ---------------- K1: entity hash bits (R8 form — best known) ---------------
__global__ __launch_bounds__(256, 1)
void k1_entity_bits(const float* __restrict__ eemb,
                    const float* __restrict__ proj, int N)
{
    extern __shared__ float sm[];
    float* projs = sm;               // 32768 floats
    float* ebuf  = sm + 32768;       // 8192 floats

    int tid  = threadIdx.x;
    int j    = tid & 127;
    int g    = tid >> 7;             // uniform per warp
    int w    = tid >> 5, lane = tid & 31;
    int t    = w & 3;

    unsigned sb_proj = smem_u32(projs) + (unsigned)(j * 4);
    unsigned sb_ebuf = smem_u32(ebuf);

    for (int i = tid; i < TT * DD * HH; i += 256) {
        int tt = i >> 13, d = (i >> 5) & 255, h = i & 31;
        projs[d * 128 + tt * 32 + h] = proj[i];
    }

    int tiles = (N + 31) >> 5;
    int per = (tiles + gridDim.x - 1) / gridDim.x;
    int t0 = blockIdx.x * per, t1 = min(tiles, t0 + per);
    if (t0 >= t1) return;

    float4 pf[8];
    {
        int base = t0 * 32;
        const float4* src = (const float4*)(eemb + (size_t)base * DD);
        int limit = min(32, N - base) * 64;
#pragma unroll
        for (int k = 0; k < 8; k++) {
            int idx = tid + k * 256;
            pf[k] = (idx < limit) ? src[idx] : make_float4(0.f, 0.f, 0.f, 0.f);
        }
    }
    __syncthreads();

    for (int tile = t0; tile < t1; tile++) {
#pragma unroll
        for (int k = 0; k < 8; k++) {
            int idx = tid + k * 256;
            int e = idx >> 6, d4 = idx & 63;
            int blk = (e >> 2) ^ (d4 & 7);
            float* dst = ebuf + d4 * 128 + blk * 4 + (e & 3);
            dst[0]  = pf[k].x;
            dst[32] = pf[k].y;
            dst[64] = pf[k].z;
            dst[96] = pf[k].w;
        }
        __syncthreads();

        if (tile + 1 < t1) {
            int base = (tile + 1) * 32;
            const float4* src = (const float4*)(eemb + (size_t)base * DD);
            int limit = min(32, N - base) * 64;
#pragma unroll
            for (int k = 0; k < 8; k++) {
                int idx = tid + k * 256;
                pf[k] = (idx < limit) ? src[idx] : make_float4(0.f, 0.f, 0.f, 0.f);
            }
        }

        unsigned long long acc[8] = {0, 0, 0, 0, 0, 0, 0, 0};
        for (int d4 = 0; d4 < 64; d4++) {
            int swz = d4 & 7;
            unsigned xb0 = (unsigned)(((g * 4 + 0) ^ swz) << 4);
            unsigned xb1 = (unsigned)(((g * 4 + 1) ^ swz) << 4);
            unsigned xb2 = (unsigned)(((g * 4 + 2) ^ swz) << 4);
            unsigned xb3 = (unsigned)(((g * 4 + 3) ^ swz) << 4);
#pragma unroll
            for (int i = 0; i < 4; i++) {
                int d = d4 * 4 + i;
                float p;
                asm("ld.shared.f32 %0, [%1];" : "=f"(p)
                    : "r"(sb_proj + (unsigned)(d * 512)));
                unsigned long long p2;
                asm("mov.b64 %0, {%1, %1};" : "=l"(p2) : "f"(p));
                unsigned eb = sb_ebuf + (unsigned)(d * 128);
                unsigned long long e0, e1;
                asm("ld.shared.v2.b64 {%0,%1}, [%2];" : "=l"(e0), "=l"(e1) : "r"(eb + xb0));
                FFMA2(acc[0], p2, e0); FFMA2(acc[1], p2, e1);
                asm("ld.shared.v2.b64 {%0,%1}, [%2];" : "=l"(e0), "=l"(e1) : "r"(eb + xb1));
                FFMA2(acc[2], p2, e0); FFMA2(acc[3], p2, e1);
                asm("ld.shared.v2.b64 {%0,%1}, [%2];" : "=l"(e0), "=l"(e1) : "r"(eb + xb2));
                FFMA2(acc[4], p2, e0); FFMA2(acc[5], p2, e1);
                asm("ld.shared.v2.b64 {%0,%1}, [%2];" : "=l"(e0), "=l"(e1) : "r"(eb + xb3));
                FFMA2(acc[6], p2, e0); FFMA2(acc[7], p2, e1);
            }
        }

        int base = tile * 32;
#pragma unroll
        for (int m = 0; m < 8; m++) {
            float lo, hi;
            asm("mov.b64 {%0,%1}, %2;" : "=f"(lo), "=f"(hi) : "l"(acc[m]));
            unsigned blo = __ballot_sync(0xffffffffu, lo > 0.f);
            unsigned bhi = __ballot_sync(0xffffffffu, hi > 0.f);
            int e0 = g * 16 + 2 * m;
            if (lane == 0) {
                if (base + e0 < N)     g_abits[(size_t)(base + e0) * 4 + t] = blo;
                if (base + e0 + 1 < N) g_abits[(size_t)(base + e0 + 1) * 4 + t] = bhi;
            }
        }
        __syncthreads();
    }
}

// ---------------- K2: hamming + histograms, 256-chunk (launch idx 3) --------
__global__ __launch_bounds__(256)
void k2_hamming(int N)
{
    extern __shared__ unsigned char smraw[];
    uint4*         sab   = (uint4*)smraw;                  // 256*16 = 4096
    unsigned*      shist = (unsigned*)(smraw + 4096);      // 64*132*4 = 33792
    unsigned char* sdist = smraw + 4096 + 33792;           // [256][68] = 17408

    int tid = threadIdx.x, w = tid >> 5, lane = tid & 31;
    int base = blockIdx.x * K2CH;
    int cnt  = min(K2CH, N - base);

    for (int i = tid; i < BMAX * 132; i += 256) shist[i] = 0u;
    for (int i = tid; i < cnt * 4; i += 256)
        ((unsigned*)sab)[i] = g_abits[(size_t)base * 4 + i];
    __syncthreads();

    for (int q = w; q < BMAX; q += 8) {       // warp exclusively owns row q
        unsigned t0 = g_tbits[q * 4 + 0], t1 = g_tbits[q * 4 + 1];
        unsigned t2 = g_tbits[q * 4 + 2], t3 = g_tbits[q * 4 + 3];
        unsigned* hrow = shist + q * 132;
        for (int it = 0; it < K2CH / 32; it++) {
            int i = it * 32 + lane;
            uint4 a = sab[i];
            unsigned d = __popc(a.x ^ t0) + __popc(a.y ^ t1)
                       + __popc(a.z ^ t2) + __popc(a.w ^ t3);
            unsigned d2 = (i < cnt) ? d : 0xffffffffu;
            if (i < cnt) sdist[i * 68 + q] = (unsigned char)d;
            unsigned mask = __match_any_sync(0xffffffffu, d2);
            if ((int)lane == __ffs(mask) - 1 && d2 != 0xffffffffu)
                hrow[d2] = hrow[d2] + __popc(mask);       // race-free: warp-owned
        }
    }
    __syncthreads();

    for (int idx = tid; idx < K2CH * 16; idx += 256) {    // packed transpose out
        int i = idx >> 4, c = idx & 15;
        if (i < cnt)
            ((unsigned*)g_dist_t)[((size_t)(base + i)) * 16 + c] =
                *(const unsigned*)(sdist + i * 68 + c * 4);
    }
    for (int i = tid; i < BMAX * 129; i += 256) {
        int q = i / 129, d = i - q * 129;
        unsigned v = shist[q * 132 + d];
        if (v) atomicAdd(&g_hist[i], v);
    }
}

// ---------------- K3a: d*, r via parallel prefix scan -----------------------
__global__ void k3a(int CAND)
{
    __shared__ unsigned s[160];
    int q = blockIdx.x, tid = threadIdx.x;
    unsigned h = (tid < 129) ? g_hist[q * 129 + tid] : 0u;
    s[tid] = h;
    __syncthreads();
#pragma unroll
    for (int off = 1; off < 160; off <<= 1) {
        unsigned v = (tid >= off) ? s[tid - off] : 0u;
        __syncthreads();
        s[tid] += v;
        __syncthreads();
    }
    unsigned cum = s[tid];
    if (tid < 129 && cum >= (unsigned)CAND && cum - h < (unsigned)CAND) {
        g_dstar[q] = tid;
        g_r[q] = CAND - (int)(cum - h);
    }
}

// ---------------- K3b: per-512-chunk count of dist == d* --------------------
__global__ __launch_bounds__(256) void k3b(int N)
{
    __shared__ unsigned char sd[K3CH * 68];
    __shared__ int sds[BMAX];
    int tid = threadIdx.x, w = tid >> 5, lane = tid & 31;
    int base = blockIdx.x * K3CH, cnt = min(K3CH, N - base);
    if (tid < BMAX) sds[tid] = g_dstar[tid];
    for (int idx = tid; idx < cnt * 16; idx += 256) {
        int i = idx >> 4, c = idx & 15;
        *(unsigned*)(sd + i * 68 + c * 4) =
            ((const unsigned*)g_dist_t)[((size_t)(base + i)) * 16 + c];
    }
    __syncthreads();
    for (int q = w; q < BMAX; q += 8) {
        int ds = sds[q]; unsigned c = 0;
        for (int it = 0; it < K3CH / 32; it++) {
            int i = it * 32 + lane;
            int f = (i < cnt) && (sd[i * 68 + q] == ds);
            c += __popc(__ballot_sync(0xffffffffu, f));
        }
        if (lane == 0) g_cnt[blockIdx.x * BMAX + q] = c;
    }
}

// ---------------- K3c: index cutoff I* --------------------------------------
__global__ void k3c(int N, int nch)
{
    __shared__ unsigned scnt[256];
    __shared__ int s_c, s_rem;
    __shared__ unsigned char fl[K3CH];
    int q = blockIdx.x, tid = threadIdx.x;
    scnt[tid] = (tid < nch) ? g_cnt[tid * BMAX + q] : 0u;
    __syncthreads();
    if (tid == 0) {
        int r = g_r[q]; unsigned cum = 0; int c = 0;
        for (;; c++) {
            unsigned h = scnt[c];
            if (cum + h >= (unsigned)r) { s_c = c; s_rem = r - (int)cum; break; }
            cum += h;
        }
    }
    __syncthreads();
    int base = s_c * K3CH, ds = g_dstar[q];
    for (int i = tid; i < K3CH; i += blockDim.x) {
        int n = base + i;
        fl[i] = (n < N && g_dist_t[(size_t)n * BMAX + q] == (unsigned char)ds) ? 1 : 0;
    }
    __syncthreads();
    if (tid == 0) {
        int need = s_rem, c2 = 0, i = 0;
        for (;; i++) { c2 += fl[i]; if (c2 == need) break; }
        g_istar[q] = base + i;
    }
}

// ---------------- K4: candidate scores — persistent (R11 proven form) -------
__global__ __launch_bounds__(256)
void k4_scores(const float* __restrict__ eemb, int N)
{
    extern __shared__ float sm4[];
    float* st   = sm4;                       // targets 64*256
    float* tile = sm4 + BMAX * DD;           // [64][32]
    int*   ds   = (int*)(tile + BMAX * 32);
    int*   is_  = ds + BMAX;

    int tid = threadIdx.x;
    for (int i = tid; i < BMAX * DD; i += blockDim.x) st[i] = g_targets[i];
    if (tid < BMAX) { ds[tid] = g_dstar[tid]; is_[tid] = g_istar[tid]; }
    __syncthreads();

    int w = tid >> 5, lane = tid & 31;
    int ntiles = (N + 31) >> 5;

    for (int tb = blockIdx.x; tb < ntiles; tb += gridDim.x) {
        int base = tb * 32;
        for (int i = tid; i < BMAX * 32; i += blockDim.x) tile[i] = -FLT_MAX;
        __syncthreads();

        for (int e = 0; e < 4; e++) {
            int i = w * 4 + e;
            int n = base + i;
            if (n >= N) continue;  // uniform per warp
            float4 r0 = *(const float4*)(eemb + (size_t)n * DD + lane * 8);
            float4 r1 = *(const float4*)(eemb + (size_t)n * DD + lane * 8 + 4);
            unsigned char d0 = g_dist_t[(size_t)n * BMAX + lane];
            unsigned char d1 = g_dist_t[(size_t)n * BMAX + 32 + lane];
            int b0 = lane, b1 = lane + 32;
            bool f0 = (d0 < ds[b0]) || (d0 == ds[b0] && n <= is_[b0]);
            bool f1 = (d1 < ds[b1]) || (d1 == ds[b1] && n <= is_[b1]);
            unsigned m0 = __ballot_sync(0xffffffffu, f0);
            unsigned m1 = __ballot_sync(0xffffffffu, f1);

            while (m0) {
                int b = __ffs(m0) - 1; m0 &= m0 - 1;
                const float4* tp = (const float4*)(st + b * DD + lane * 8);
                float4 t0 = tp[0], t1 = tp[1];
                float s = r0.x * t0.x + r0.y * t0.y + r0.z * t0.z + r0.w * t0.w
                        + r1.x * t1.x + r1.y * t1.y + r1.z * t1.z + r1.w * t1.w;
#pragma unroll
                for (int off = 16; off; off >>= 1) s += __shfl_xor_sync(0xffffffffu, s, off);
                if (lane == 0) tile[b * 32 + i] = s;
            }
            while (m1) {
                int b = 32 + __ffs(m1) - 1; m1 &= m1 - 1;
                const float4* tp = (const float4*)(st + b * DD + lane * 8);
                float4 t0 = tp[0], t1 = tp[1];
                float s = r0.x * t0.x + r0.y * t0.y + r0.z * t0.z + r0.w * t0.w
                        + r1.x * t1.x + r1.y * t1.y + r1.z * t1.z + r1.w * t1.w;
#pragma unroll
                for (int off = 16; off; off >>= 1) s += __shfl_xor_sync(0xffffffffu, s, off);
                if (lane == 0) tile[b * 32 + i] = s;
            }
        }
        __syncthreads();
        for (int idx = tid; idx < BMAX * 32; idx += blockDim.x) {
            int bb = idx >> 5, i = idx & 31;
            int n = base + i;
            if (n < N) g_scores[(size_t)bb * N + n] = tile[idx];
        }
        __syncthreads();
    }
}

// ---------------- K5a: per-segment top-10 in smem ---------------------------
#define SEG 6250
__global__ __launch_bounds__(256) void k5a(int N)
{
    extern __shared__ float sv[];            // SEG floats
    __shared__ float wv[8]; __shared__ int wi[8];
    int b = blockIdx.x >> 4, s = blockIdx.x & 15;
    int tid = threadIdx.x, w = tid >> 5, lane = tid & 31;
    int base = s * SEG;
    const float* src = g_scores + (size_t)b * N;
    for (int i = tid; i < SEG; i += 256)
        sv[i] = (base + i < N) ? src[base + i] : -FLT_MAX;
    __syncthreads();

    for (int p = 0; p < 10; p++) {
        float bv = -FLT_MAX; int bi = 1 << 30;
        for (int i = tid; i < SEG; i += 256) {
            float v = sv[i];
            if (v > bv) { bv = v; bi = i; }
        }
#pragma unroll
        for (int off = 16; off; off >>= 1) {
            float ov = __shfl_down_sync(0xffffffffu, bv, off);
            int   oi = __shfl_down_sync(0xffffffffu, bi, off);
            if (ov > bv || (ov == bv && oi < bi)) { bv = ov; bi = oi; }
        }
        if (lane == 0) { wv[w] = bv; wi[w] = bi; }
        __syncthreads();
        if (tid == 0) {
            float fv = wv[0]; int fi = wi[0];
            for (int x = 1; x < 8; x++)
                if (wv[x] > fv || (wv[x] == fv && wi[x] < fi)) { fv = wv[x]; fi = wi[x]; }
            g_pv[blockIdx.x * 10 + p] = fv;
            g_pi[blockIdx.x * 10 + p] = base + ((fi < SEG) ? fi : 0);
            if (fi < SEG) sv[fi] = -FLT_MAX;
        }
        __syncthreads();
    }
}

// ---------------- K5b: merge 16x10 -> top-k (one warp per query) ------------
__global__ void k5b(const int* __restrict__ kptr, float* __restrict__ out, int half)
{
    __shared__ float sv[160]; __shared__ int si[160];
    int b = blockIdx.x, tid = threadIdx.x;
    int kk = kptr[0];
    for (int i = tid; i < 160; i += 32) { sv[i] = g_pv[b * 160 + i]; si[i] = g_pi[b * 160 + i]; }
    __syncwarp();
    for (int p = 0; p < kk; p++) {
        float bv = -FLT_MAX; int bi = 0x7fffffff, bs = -1;
        for (int i = tid; i < 160; i += 32) {
            float v = sv[i]; int ix = si[i];
            if (v > bv || (v == bv && ix < bi)) { bv = v; bi = ix; bs = i; }
        }
#pragma unroll
        for (int off = 16; off; off >>= 1) {
            float ov = __shfl_down_sync(0xffffffffu, bv, off);
            int   oi = __shfl_down_sync(0xffffffffu, bi, off);
            int   os = __shfl_down_sync(0xffffffffu, bs, off);
            if (ov > bv || (ov == bv && oi < bi)) { bv = ov; bi = oi; bs = os; }
        }
        bs = __shfl_sync(0xffffffffu, bs, 0);
        if (tid == 0) {
            out[b * kk + p]        = (float)bi;
            out[half + b * kk + p] = bv;
            if (bs >= 0) sv[bs] = -FLT_MAX;
        }
        __syncwarp();
    }
}

// ---------------- launch ----------------------------------------------------
extern "C" void kernel_launch(void* const* d_in, const int* in_sizes, int n_in,
                              void* d_out, int out_size)
{
    const int*   head = (const int*)d_in[0];
    const int*   rel  = (const int*)d_in[1];
    const float* eemb = (const float*)d_in[2];
    const float* remb = (const float*)d_in[3];
    const float* proj = (const float*)d_in[4];
    const int*   kptr = (const int*)d_in[5];

    int B = in_sizes[0];
    int N = in_sizes[2] / DD;
    int CAND = N / 10; if (CAND < 100) CAND = 100;
    int nch2 = (N + K2CH - 1) / K2CH;   // 392
    int nch3 = (N + K3CH - 1) / K3CH;   // 196

    cudaFuncSetAttribute(k1_entity_bits, cudaFuncAttributeMaxDynamicSharedMemorySize, 164 * 1024);
    cudaFuncSetAttribute(k2_hamming,     cudaFuncAttributeMaxDynamicSharedMemorySize, 60 * 1024);
    cudaFuncSetAttribute(k4_scores,      cudaFuncAttributeMaxDynamicSharedMemorySize, 80 * 1024);

    size_t k1_smem = (32768 + 8192) * sizeof(float);                 // 163840
    size_t k2_smem = 4096 + BMAX * 132 * 4 + (size_t)K2CH * 68;      // 55296
    size_t k4_smem = (BMAX * DD + BMAX * 32) * sizeof(float) + 2 * BMAX * sizeof(int);
    size_t k5_smem = SEG * sizeof(float);                            // 25000

    // launch order: idx 3 = k2 (profiled — verifies the 256-chunk change)
    k0m_targets<<<B, 128>>>(head, rel, eemb, remb);                  // idx 0
    k0b_tbits<<<B, 128>>>(proj);                                     // idx 1
    k1_entity_bits<<<148, 256, k1_smem>>>(eemb, proj, N);            // idx 2
    k2_hamming<<<nch2, 256, k2_smem>>>(N);                           // idx 3 (profiled)
    k3a<<<BMAX, 160>>>(CAND);
    k3b<<<nch3, 256>>>(N);
    k3c<<<BMAX, 256>>>(N, nch3);
    k4_scores<<<444, 256, k4_smem>>>(eemb, N);
    k5a<<<BMAX * 16, 256, k5_smem>>>(N);
    k5b<<<BMAX, 32>>>(kptr, (float*)d_out, out_size / 2);
}

// round 15
// speedup vs baseline: 1.3577x; 1.0049x over previous
#include <cuda_runtime.h>
#include <cstdint>
#include <cfloat>

#define NMAX 100000
#define BMAX 64
#define DD   256
#define TT   4
#define HH   32
#define K2CH 256   // k2 chunk (4 blocks/SM)
#define K3CH 512   // k3b/k3c chunk

// ---------------- scratch (static __device__, no allocation) ----------------
__device__ float         g_targets[BMAX * DD];
__device__ unsigned      g_tbits[BMAX * 4];
__device__ unsigned      g_abits[NMAX * 4];
__device__ unsigned char g_dist_t[(size_t)NMAX * BMAX];   // [n][b]
__device__ unsigned      g_hist[BMAX * 129];
__device__ int           g_dstar[BMAX];
__device__ int           g_r[BMAX];
__device__ int           g_istar[BMAX];
__device__ unsigned      g_cnt[200 * BMAX];               // [chunk512][b]
__device__ float         g_scores[(size_t)BMAX * NMAX];   // [b][n]
__device__ float         g_pv[BMAX * 16 * 10];
__device__ int           g_pi[BMAX * 16 * 10];

__device__ __forceinline__ unsigned smem_u32(const void* p) {
    unsigned a;
    asm("{ .reg .u64 t; cvta.to.shared.u64 t, %1; cvt.u32.u64 %0, t; }"
        : "=r"(a) : "l"(p));
    return a;
}
#define FFMA2(acc, a, b) \
    asm("fma.rn.f32x2 %0, %1, %2, %0;" : "+l"(acc) : "l"(a), "l"(b))

// ---------------- K0m: targets + zero hist (launch idx 0) -------------------
__global__ void k0m_targets(const int* __restrict__ head,
                            const int* __restrict__ rel,
                            const float* __restrict__ eemb,
                            const float* __restrict__ remb)
{
    int b = blockIdx.x, tid = threadIdx.x;
    int hh = head[b], rr = rel[b];
    for (int d = tid; d < DD; d += blockDim.x)
        g_targets[b * DD + d] = eemb[(size_t)hh * DD + d] * remb[(size_t)rr * DD + d];
    for (int i = tid; i < 129; i += blockDim.x) g_hist[b * 129 + i] = 0u;
}

// ---------------- K0b: target hash bits (launch idx 1) ----------------------
__global__ void k0b_tbits(const float* __restrict__ proj)
{
    __shared__ float tgt[DD];
    int b = blockIdx.x, tid = threadIdx.x;
    for (int d = tid; d < DD; d += blockDim.x) tgt[d] = g_targets[b * DD + d];
    __syncthreads();
    int t = tid >> 5, lane = tid & 31;
    const float* pp = proj + (size_t)t * DD * HH + lane;
    float acc = 0.f;
#pragma unroll 8
    for (int d = 0; d < DD; d++) acc += tgt[d] * pp[d * HH];
    unsigned w = __ballot_sync(0xffffffffu, acc > 0.f);
    if (lane == 0) g_tbits[b * 4 + t] = w;
}

// ---------------- K1: entity hash bits (R8 form — best known) ---------------
__global__ __launch_bounds__(256, 1)
void k1_entity_bits(const float* __restrict__ eemb,
                    const float* __restrict__ proj, int N)
{
    extern __shared__ float sm[];
    float* projs = sm;               // 32768 floats
    float* ebuf  = sm + 32768;       // 8192 floats

    int tid  = threadIdx.x;
    int j    = tid & 127;
    int g    = tid >> 7;             // uniform per warp
    int w    = tid >> 5, lane = tid & 31;
    int t    = w & 3;

    unsigned sb_proj = smem_u32(projs) + (unsigned)(j * 4);
    unsigned sb_ebuf = smem_u32(ebuf);

    for (int i = tid; i < TT * DD * HH; i += 256) {
        int tt = i >> 13, d = (i >> 5) & 255, h = i & 31;
        projs[d * 128 + tt * 32 + h] = proj[i];
    }

    int tiles = (N + 31) >> 5;
    int per = (tiles + gridDim.x - 1) / gridDim.x;
    int t0 = blockIdx.x * per, t1 = min(tiles, t0 + per);
    if (t0 >= t1) return;

    float4 pf[8];
    {
        int base = t0 * 32;
        const float4* src = (const float4*)(eemb + (size_t)base * DD);
        int limit = min(32, N - base) * 64;
#pragma unroll
        for (int k = 0; k < 8; k++) {
            int idx = tid + k * 256;
            pf[k] = (idx < limit) ? src[idx] : make_float4(0.f, 0.f, 0.f, 0.f);
        }
    }
    __syncthreads();

    for (int tile = t0; tile < t1; tile++) {
#pragma unroll
        for (int k = 0; k < 8; k++) {
            int idx = tid + k * 256;
            int e = idx >> 6, d4 = idx & 63;
            int blk = (e >> 2) ^ (d4 & 7);
            float* dst = ebuf + d4 * 128 + blk * 4 + (e & 3);
            dst[0]  = pf[k].x;
            dst[32] = pf[k].y;
            dst[64] = pf[k].z;
            dst[96] = pf[k].w;
        }
        __syncthreads();

        if (tile + 1 < t1) {
            int base = (tile + 1) * 32;
            const float4* src = (const float4*)(eemb + (size_t)base * DD);
            int limit = min(32, N - base) * 64;
#pragma unroll
            for (int k = 0; k < 8; k++) {
                int idx = tid + k * 256;
                pf[k] = (idx < limit) ? src[idx] : make_float4(0.f, 0.f, 0.f, 0.f);
            }
        }

        unsigned long long acc[8] = {0, 0, 0, 0, 0, 0, 0, 0};
        for (int d4 = 0; d4 < 64; d4++) {
            int swz = d4 & 7;
            unsigned xb0 = (unsigned)(((g * 4 + 0) ^ swz) << 4);
            unsigned xb1 = (unsigned)(((g * 4 + 1) ^ swz) << 4);
            unsigned xb2 = (unsigned)(((g * 4 + 2) ^ swz) << 4);
            unsigned xb3 = (unsigned)(((g * 4 + 3) ^ swz) << 4);
#pragma unroll
            for (int i = 0; i < 4; i++) {
                int d = d4 * 4 + i;
                float p;
                asm("ld.shared.f32 %0, [%1];" : "=f"(p)
                    : "r"(sb_proj + (unsigned)(d * 512)));
                unsigned long long p2;
                asm("mov.b64 %0, {%1, %1};" : "=l"(p2) : "f"(p));
                unsigned eb = sb_ebuf + (unsigned)(d * 128);
                unsigned long long e0, e1;
                asm("ld.shared.v2.b64 {%0,%1}, [%2];" : "=l"(e0), "=l"(e1) : "r"(eb + xb0));
                FFMA2(acc[0], p2, e0); FFMA2(acc[1], p2, e1);
                asm("ld.shared.v2.b64 {%0,%1}, [%2];" : "=l"(e0), "=l"(e1) : "r"(eb + xb1));
                FFMA2(acc[2], p2, e0); FFMA2(acc[3], p2, e1);
                asm("ld.shared.v2.b64 {%0,%1}, [%2];" : "=l"(e0), "=l"(e1) : "r"(eb + xb2));
                FFMA2(acc[4], p2, e0); FFMA2(acc[5], p2, e1);
                asm("ld.shared.v2.b64 {%0,%1}, [%2];" : "=l"(e0), "=l"(e1) : "r"(eb + xb3));
                FFMA2(acc[6], p2, e0); FFMA2(acc[7], p2, e1);
            }
        }

        int base = tile * 32;
#pragma unroll
        for (int m = 0; m < 8; m++) {
            float lo, hi;
            asm("mov.b64 {%0,%1}, %2;" : "=f"(lo), "=f"(hi) : "l"(acc[m]));
            unsigned blo = __ballot_sync(0xffffffffu, lo > 0.f);
            unsigned bhi = __ballot_sync(0xffffffffu, hi > 0.f);
            int e0 = g * 16 + 2 * m;
            if (lane == 0) {
                if (base + e0 < N)     g_abits[(size_t)(base + e0) * 4 + t] = blo;
                if (base + e0 + 1 < N) g_abits[(size_t)(base + e0 + 1) * 4 + t] = bhi;
            }
        }
        __syncthreads();
    }
}

// ---------------- K2: hamming + histograms, 256-chunk (launch idx 3) --------
__global__ __launch_bounds__(256)
void k2_hamming(int N)
{
    extern __shared__ unsigned char smraw[];
    uint4*         sab   = (uint4*)smraw;                  // 256*16 = 4096
    unsigned*      shist = (unsigned*)(smraw + 4096);      // 64*132*4 = 33792
    unsigned char* sdist = smraw + 4096 + 33792;           // [256][68] = 17408

    int tid = threadIdx.x, w = tid >> 5, lane = tid & 31;
    int base = blockIdx.x * K2CH;
    int cnt  = min(K2CH, N - base);

    for (int i = tid; i < BMAX * 132; i += 256) shist[i] = 0u;
    for (int i = tid; i < cnt * 4; i += 256)
        ((unsigned*)sab)[i] = g_abits[(size_t)base * 4 + i];
    __syncthreads();

    for (int q = w; q < BMAX; q += 8) {       // warp exclusively owns row q
        unsigned t0 = g_tbits[q * 4 + 0], t1 = g_tbits[q * 4 + 1];
        unsigned t2 = g_tbits[q * 4 + 2], t3 = g_tbits[q * 4 + 3];
        unsigned* hrow = shist + q * 132;
        for (int it = 0; it < K2CH / 32; it++) {
            int i = it * 32 + lane;
            uint4 a = sab[i];
            unsigned d = __popc(a.x ^ t0) + __popc(a.y ^ t1)
                       + __popc(a.z ^ t2) + __popc(a.w ^ t3);
            unsigned d2 = (i < cnt) ? d : 0xffffffffu;
            if (i < cnt) sdist[i * 68 + q] = (unsigned char)d;
            unsigned mask = __match_any_sync(0xffffffffu, d2);
            if ((int)lane == __ffs(mask) - 1 && d2 != 0xffffffffu)
                hrow[d2] = hrow[d2] + __popc(mask);       // race-free: warp-owned
        }
    }
    __syncthreads();

    for (int idx = tid; idx < K2CH * 16; idx += 256) {    // packed transpose out
        int i = idx >> 4, c = idx & 15;
        if (i < cnt)
            ((unsigned*)g_dist_t)[((size_t)(base + i)) * 16 + c] =
                *(const unsigned*)(sdist + i * 68 + c * 4);
    }
    for (int i = tid; i < BMAX * 129; i += 256) {
        int q = i / 129, d = i - q * 129;
        unsigned v = shist[q * 132 + d];
        if (v) atomicAdd(&g_hist[i], v);
    }
}

// ---------------- K3a: d*, r via parallel prefix scan -----------------------
__global__ void k3a(int CAND)
{
    __shared__ unsigned s[160];
    int q = blockIdx.x, tid = threadIdx.x;
    unsigned h = (tid < 129) ? g_hist[q * 129 + tid] : 0u;
    s[tid] = h;
    __syncthreads();
#pragma unroll
    for (int off = 1; off < 160; off <<= 1) {
        unsigned v = (tid >= off) ? s[tid - off] : 0u;
        __syncthreads();
        s[tid] += v;
        __syncthreads();
    }
    unsigned cum = s[tid];
    if (tid < 129 && cum >= (unsigned)CAND && cum - h < (unsigned)CAND) {
        g_dstar[q] = tid;
        g_r[q] = CAND - (int)(cum - h);
    }
}

// ---------------- K3b: per-512-chunk count of dist == d* --------------------
__global__ __launch_bounds__(256) void k3b(int N)
{
    __shared__ unsigned char sd[K3CH * 68];
    __shared__ int sds[BMAX];
    int tid = threadIdx.x, w = tid >> 5, lane = tid & 31;
    int base = blockIdx.x * K3CH, cnt = min(K3CH, N - base);
    if (tid < BMAX) sds[tid] = g_dstar[tid];
    for (int idx = tid; idx < cnt * 16; idx += 256) {
        int i = idx >> 4, c = idx & 15;
        *(unsigned*)(sd + i * 68 + c * 4) =
            ((const unsigned*)g_dist_t)[((size_t)(base + i)) * 16 + c];
    }
    __syncthreads();
    for (int q = w; q < BMAX; q += 8) {
        int ds = sds[q]; unsigned c = 0;
        for (int it = 0; it < K3CH / 32; it++) {
            int i = it * 32 + lane;
            int f = (i < cnt) && (sd[i * 68 + q] == ds);
            c += __popc(__ballot_sync(0xffffffffu, f));
        }
        if (lane == 0) g_cnt[blockIdx.x * BMAX + q] = c;
    }
}

// ---------------- K3c: index cutoff I* --------------------------------------
__global__ void k3c(int N, int nch)
{
    __shared__ unsigned scnt[256];
    __shared__ int s_c, s_rem;
    __shared__ unsigned char fl[K3CH];
    int q = blockIdx.x, tid = threadIdx.x;
    scnt[tid] = (tid < nch) ? g_cnt[tid * BMAX + q] : 0u;
    __syncthreads();
    if (tid == 0) {
        int r = g_r[q]; unsigned cum = 0; int c = 0;
        for (;; c++) {
            unsigned h = scnt[c];
            if (cum + h >= (unsigned)r) { s_c = c; s_rem = r - (int)cum; break; }
            cum += h;
        }
    }
    __syncthreads();
    int base = s_c * K3CH, ds = g_dstar[q];
    for (int i = tid; i < K3CH; i += blockDim.x) {
        int n = base + i;
        fl[i] = (n < N && g_dist_t[(size_t)n * BMAX + q] == (unsigned char)ds) ? 1 : 0;
    }
    __syncthreads();
    if (tid == 0) {
        int need = s_rem, c2 = 0, i = 0;
        for (;; i++) { c2 += fl[i]; if (c2 == need) break; }
        g_istar[q] = base + i;
    }
}

// ---------------- K4: candidate scores — persistent, 2-wide candidate ILP ---
__global__ __launch_bounds__(256)
void k4_scores(const float* __restrict__ eemb, int N)
{
    extern __shared__ float sm4[];
    float* st   = sm4;                       // targets 64*256
    float* tile = sm4 + BMAX * DD;           // [64][32]
    int*   ds   = (int*)(tile + BMAX * 32);
    int*   is_  = ds + BMAX;

    int tid = threadIdx.x;
    for (int i = tid; i < BMAX * DD; i += blockDim.x) st[i] = g_targets[i];
    if (tid < BMAX) { ds[tid] = g_dstar[tid]; is_[tid] = g_istar[tid]; }
    __syncthreads();

    int w = tid >> 5, lane = tid & 31;
    int ntiles = (N + 31) >> 5;

    for (int tb = blockIdx.x; tb < ntiles; tb += gridDim.x) {
        int base = tb * 32;
        for (int i = tid; i < BMAX * 32; i += blockDim.x) tile[i] = -FLT_MAX;
        __syncthreads();

        for (int e = 0; e < 4; e++) {
            int i = w * 4 + e;
            int n = base + i;
            if (n >= N) continue;  // uniform per warp
            float4 r0 = *(const float4*)(eemb + (size_t)n * DD + lane * 8);
            float4 r1 = *(const float4*)(eemb + (size_t)n * DD + lane * 8 + 4);
            unsigned char d0 = g_dist_t[(size_t)n * BMAX + lane];
            unsigned char d1 = g_dist_t[(size_t)n * BMAX + 32 + lane];
            int b0 = lane, b1 = lane + 32;
            bool f0 = (d0 < ds[b0]) || (d0 == ds[b0] && n <= is_[b0]);
            bool f1 = (d1 < ds[b1]) || (d1 == ds[b1] && n <= is_[b1]);
            unsigned m0 = __ballot_sync(0xffffffffu, f0);
            unsigned m1 = __ballot_sync(0xffffffffu, f1);

            // process candidate queries 2 at a time: independent shfl trees pipeline
            while (m0) {
                int ba = __ffs(m0) - 1; m0 &= m0 - 1;
                int bb = -1;
                if (m0) { bb = __ffs(m0) - 1; m0 &= m0 - 1; }
                int bbc = (bb >= 0) ? bb : ba;
                const float4* ta = (const float4*)(st + ba * DD + lane * 8);
                const float4* tb2 = (const float4*)(st + bbc * DD + lane * 8);
                float4 a0 = ta[0], a1 = ta[1];
                float4 c0 = tb2[0], c1 = tb2[1];
                float sa = r0.x * a0.x + r0.y * a0.y + r0.z * a0.z + r0.w * a0.w
                         + r1.x * a1.x + r1.y * a1.y + r1.z * a1.z + r1.w * a1.w;
                float sb = r0.x * c0.x + r0.y * c0.y + r0.z * c0.z + r0.w * c0.w
                         + r1.x * c1.x + r1.y * c1.y + r1.z * c1.z + r1.w * c1.w;
#pragma unroll
                for (int off = 16; off; off >>= 1) {
                    sa += __shfl_xor_sync(0xffffffffu, sa, off);
                    sb += __shfl_xor_sync(0xffffffffu, sb, off);
                }
                if (lane == 0) {
                    tile[ba * 32 + i] = sa;
                    if (bb >= 0) tile[bb * 32 + i] = sb;
                }
            }
            while (m1) {
                int ba = 32 + __ffs(m1) - 1; m1 &= m1 - 1;
                int bb = -1;
                if (m1) { bb = 32 + __ffs(m1) - 1; m1 &= m1 - 1; }
                int bbc = (bb >= 0) ? bb : ba;
                const float4* ta = (const float4*)(st + ba * DD + lane * 8);
                const float4* tb2 = (const float4*)(st + bbc * DD + lane * 8);
                float4 a0 = ta[0], a1 = ta[1];
                float4 c0 = tb2[0], c1 = tb2[1];
                float sa = r0.x * a0.x + r0.y * a0.y + r0.z * a0.z + r0.w * a0.w
                         + r1.x * a1.x + r1.y * a1.y + r1.z * a1.z + r1.w * a1.w;
                float sb = r0.x * c0.x + r0.y * c0.y + r0.z * c0.z + r0.w * c0.w
                         + r1.x * c1.x + r1.y * c1.y + r1.z * c1.z + r1.w * c1.w;
#pragma unroll
                for (int off = 16; off; off >>= 1) {
                    sa += __shfl_xor_sync(0xffffffffu, sa, off);
                    sb += __shfl_xor_sync(0xffffffffu, sb, off);
                }
                if (lane == 0) {
                    tile[ba * 32 + i] = sa;
                    if (bb >= 0) tile[bb * 32 + i] = sb;
                }
            }
        }
        __syncthreads();
        for (int idx = tid; idx < BMAX * 32; idx += blockDim.x) {
            int bb = idx >> 5, i = idx & 31;
            int n = base + i;
            if (n < N) g_scores[(size_t)bb * N + n] = tile[idx];
        }
        __syncthreads();
    }
}

// ---------------- K5a: per-segment top-10 in smem ---------------------------
#define SEG 6250
__global__ __launch_bounds__(256) void k5a(int N)
{
    extern __shared__ float sv[];            // SEG floats
    __shared__ float wv[8]; __shared__ int wi[8];
    int b = blockIdx.x >> 4, s = blockIdx.x & 15;
    int tid = threadIdx.x, w = tid >> 5, lane = tid & 31;
    int base = s * SEG;
    const float* src = g_scores + (size_t)b * N;
    for (int i = tid; i < SEG; i += 256)
        sv[i] = (base + i < N) ? src[base + i] : -FLT_MAX;
    __syncthreads();

    for (int p = 0; p < 10; p++) {
        float bv = -FLT_MAX; int bi = 1 << 30;
        for (int i = tid; i < SEG; i += 256) {
            float v = sv[i];
            if (v > bv) { bv = v; bi = i; }
        }
#pragma unroll
        for (int off = 16; off; off >>= 1) {
            float ov = __shfl_down_sync(0xffffffffu, bv, off);
            int   oi = __shfl_down_sync(0xffffffffu, bi, off);
            if (ov > bv || (ov == bv && oi < bi)) { bv = ov; bi = oi; }
        }
        if (lane == 0) { wv[w] = bv; wi[w] = bi; }
        __syncthreads();
        if (tid == 0) {
            float fv = wv[0]; int fi = wi[0];
            for (int x = 1; x < 8; x++)
                if (wv[x] > fv || (wv[x] == fv && wi[x] < fi)) { fv = wv[x]; fi = wi[x]; }
            g_pv[blockIdx.x * 10 + p] = fv;
            g_pi[blockIdx.x * 10 + p] = base + ((fi < SEG) ? fi : 0);
            if (fi < SEG) sv[fi] = -FLT_MAX;
        }
        __syncthreads();
    }
}

// ---------------- K5b: merge 16x10 -> top-k (one warp per query) ------------
__global__ void k5b(const int* __restrict__ kptr, float* __restrict__ out, int half)
{
    __shared__ float sv[160]; __shared__ int si[160];
    int b = blockIdx.x, tid = threadIdx.x;
    int kk = kptr[0];
    for (int i = tid; i < 160; i += 32) { sv[i] = g_pv[b * 160 + i]; si[i] = g_pi[b * 160 + i]; }
    __syncwarp();
    for (int p = 0; p < kk; p++) {
        float bv = -FLT_MAX; int bi = 0x7fffffff, bs = -1;
        for (int i = tid; i < 160; i += 32) {
            float v = sv[i]; int ix = si[i];
            if (v > bv || (v == bv && ix < bi)) { bv = v; bi = ix; bs = i; }
        }
#pragma unroll
        for (int off = 16; off; off >>= 1) {
            float ov = __shfl_down_sync(0xffffffffu, bv, off);
            int   oi = __shfl_down_sync(0xffffffffu, bi, off);
            int   os = __shfl_down_sync(0xffffffffu, bs, off);
            if (ov > bv || (ov == bv && oi < bi)) { bv = ov; bi = oi; bs = os; }
        }
        bs = __shfl_sync(0xffffffffu, bs, 0);
        if (tid == 0) {
            out[b * kk + p]        = (float)bi;
            out[half + b * kk + p] = bv;
            if (bs >= 0) sv[bs] = -FLT_MAX;
        }
        __syncwarp();
    }
}

// ---------------- launch ----------------------------------------------------
extern "C" void kernel_launch(void* const* d_in, const int* in_sizes, int n_in,
                              void* d_out, int out_size)
{
    const int*   head = (const int*)d_in[0];
    const int*   rel  = (const int*)d_in[1];
    const float* eemb = (const float*)d_in[2];
    const float* remb = (const float*)d_in[3];
    const float* proj = (const float*)d_in[4];
    const int*   kptr = (const int*)d_in[5];

    int B = in_sizes[0];
    int N = in_sizes[2] / DD;
    int CAND = N / 10; if (CAND < 100) CAND = 100;
    int nch2 = (N + K2CH - 1) / K2CH;   // 391
    int nch3 = (N + K3CH - 1) / K3CH;   // 196

    cudaFuncSetAttribute(k1_entity_bits, cudaFuncAttributeMaxDynamicSharedMemorySize, 164 * 1024);
    cudaFuncSetAttribute(k2_hamming,     cudaFuncAttributeMaxDynamicSharedMemorySize, 60 * 1024);
    cudaFuncSetAttribute(k4_scores,      cudaFuncAttributeMaxDynamicSharedMemorySize, 80 * 1024);

    size_t k1_smem = (32768 + 8192) * sizeof(float);                 // 163840
    size_t k2_smem = 4096 + BMAX * 132 * 4 + (size_t)K2CH * 68;      // 55296
    size_t k4_smem = (BMAX * DD + BMAX * 32) * sizeof(float) + 2 * BMAX * sizeof(int);
    size_t k5_smem = SEG * sizeof(float);                            // 25000

    // launch order: idx 3 = k2 (capture slot; stability check)
    k0m_targets<<<B, 128>>>(head, rel, eemb, remb);                  // idx 0
    k0b_tbits<<<B, 128>>>(proj);                                     // idx 1
    k1_entity_bits<<<148, 256, k1_smem>>>(eemb, proj, N);            // idx 2
    k2_hamming<<<nch2, 256, k2_smem>>>(N);                           // idx 3 (profiled)
    k3a<<<BMAX, 160>>>(CAND);
    k3b<<<nch3, 256>>>(N);
    k3c<<<BMAX, 256>>>(N, nch3);
    k4_scores<<<444, 256, k4_smem>>>(eemb, N);
    k5a<<<BMAX * 16, 256, k5_smem>>>(N);
    k5b<<<BMAX, 32>>>(kptr, (float*)d_out, out_size / 2);
}